// round 12
// baseline (speedup 1.0000x reference)
#include <cuda_runtime.h>
#include <cuda_bf16.h>
#include <math.h>
#include <stdint.h>

#define DMODEL 1024
#define NHEAD  16
#define HD     64
#define NB     4
#define SQ     1024
#define SK     2048

// ---------------------------------------------------------------------------
// Scratch (__device__ globals: allocation-free rule)
// ---------------------------------------------------------------------------
__device__ __nv_bfloat16 g_qh[NB * SQ * DMODEL];
__device__ __nv_bfloat16 g_ql[NB * SQ * DMODEL];
__device__ __nv_bfloat16 g_kvh[NB * SK * DMODEL];
__device__ __nv_bfloat16 g_kvl[NB * SK * DMODEL];
__device__ __nv_bfloat16 g_oh[NB * SQ * DMODEL];
__device__ __nv_bfloat16 g_ol[NB * SQ * DMODEL];
__device__ __nv_bfloat16 g_wqh[DMODEL * DMODEL];
__device__ __nv_bfloat16 g_wql[DMODEL * DMODEL];
__device__ __nv_bfloat16 g_wkh[DMODEL * DMODEL];
__device__ __nv_bfloat16 g_wkl[DMODEL * DMODEL];
__device__ __nv_bfloat16 g_wvh[DMODEL * DMODEL];
__device__ __nv_bfloat16 g_wvl[DMODEL * DMODEL];
__device__ __nv_bfloat16 g_woh[DMODEL * DMODEL];
__device__ __nv_bfloat16 g_wol[DMODEL * DMODEL];

// attention operands (bf16 hi/lo, post-RoPE, written by fused gemm epilogues)
__device__ __nv_bfloat16 g_aqh[NB * SQ * DMODEL];
__device__ __nv_bfloat16 g_aql[NB * SQ * DMODEL];
__device__ __nv_bfloat16 g_akh[NB * SK * DMODEL];
__device__ __nv_bfloat16 g_akl[NB * SK * DMODEL];
__device__ __nv_bfloat16 g_avh[NB * SK * DMODEL];
__device__ __nv_bfloat16 g_avl[NB * SK * DMODEL];

// ---------------------------------------------------------------------------
// Helpers
// ---------------------------------------------------------------------------
__device__ __forceinline__ uint32_t smem_u32(const void* p) {
    uint32_t a;
    asm("{ .reg .u64 t; cvta.to.shared.u64 t, %1; cvt.u32.u64 %0, t; }" : "=r"(a) : "l"(p));
    return a;
}
__device__ __forceinline__ void cp16(uint32_t dst, const void* src) {
    asm volatile("cp.async.cg.shared.global [%0], [%1], 16;" :: "r"(dst), "l"(src));
}
__device__ __forceinline__ void cp_commit() {
    asm volatile("cp.async.commit_group;" ::: "memory");
}
__device__ __forceinline__ void cp_wait1() {
    asm volatile("cp.async.wait_group 1;" ::: "memory");
}
__device__ __forceinline__ void cp_wait0() {
    asm volatile("cp.async.wait_group 0;" ::: "memory");
}
__device__ __forceinline__ void ldsm_x4(uint32_t addr, uint32_t* r) {
    asm volatile("ldmatrix.sync.aligned.m8n8.x4.shared.b16 {%0,%1,%2,%3}, [%4];"
                 : "=r"(r[0]), "=r"(r[1]), "=r"(r[2]), "=r"(r[3]) : "r"(addr));
}
__device__ __forceinline__ void ldsm_x4t(uint32_t addr, uint32_t* r) {
    asm volatile("ldmatrix.sync.aligned.m8n8.x4.trans.shared.b16 {%0,%1,%2,%3}, [%4];"
                 : "=r"(r[0]), "=r"(r[1]), "=r"(r[2]), "=r"(r[3]) : "r"(addr));
}
__device__ __forceinline__ void mma_bf16(float* d, const uint32_t* a, uint32_t b0, uint32_t b1) {
    asm volatile(
        "mma.sync.aligned.m16n8k16.row.col.f32.bf16.bf16.f32 "
        "{%0,%1,%2,%3}, {%4,%5,%6,%7}, {%8,%9}, {%0,%1,%2,%3};"
        : "+f"(d[0]), "+f"(d[1]), "+f"(d[2]), "+f"(d[3])
        : "r"(a[0]), "r"(a[1]), "r"(a[2]), "r"(a[3]), "r"(b0), "r"(b1));
}
// exp on the FMA pipe: 2^(x*log2e), deg-5 poly. rel err ~5e-7.
__device__ __forceinline__ float fast_exp(float x) {
    float y = fmaxf(x * 1.4426950408889634f, -100.0f);
    int n = __float2int_rn(y);
    float f = y - (float)n;
    float p = 1.3333558146e-3f;
    p = fmaf(p, f, 9.6181291076e-3f);
    p = fmaf(p, f, 5.5504108665e-2f);
    p = fmaf(p, f, 2.4022650696e-1f);
    p = fmaf(p, f, 6.9314718056e-1f);
    p = fmaf(p, f, 1.0f);
    return __int_as_float(__float_as_int(p) + (n << 23));
}
// split (a,b) fp32 pair -> bf16x2 hi + bf16x2 lo (lo = residual)
__device__ __forceinline__ void pack_split(float a, float b, uint32_t& hi2, uint32_t& lo2) {
    __nv_bfloat162 hb = __float22bfloat162_rn(make_float2(a, b));
    uint32_t h;
    memcpy(&h, &hb, 4);
    float ra = a - __uint_as_float(h << 16);
    float rb = b - __uint_as_float(h & 0xFFFF0000u);
    __nv_bfloat162 lb = __float22bfloat162_rn(make_float2(ra, rb));
    uint32_t l;
    memcpy(&l, &lb, 4);
    hi2 = h; lo2 = l;
}

// ---------------------------------------------------------------------------
// fp32 -> (bf16 hi, bf16 lo) split for ONE array
// ---------------------------------------------------------------------------
__global__ void split_kernel(const float* __restrict__ x, __nv_bfloat16* __restrict__ hi,
                             __nv_bfloat16* __restrict__ lo, int n)
{
    int i = (blockIdx.x * blockDim.x + threadIdx.x) * 4;
    if (i >= n) return;
    float4 v = *(const float4*)(x + i);
    uint32_t h0, l0, h1, l1;
    pack_split(v.x, v.y, h0, l0);
    pack_split(v.z, v.w, h1, l1);
    *(uint2*)(hi + i) = make_uint2(h0, h1);
    *(uint2*)(lo + i) = make_uint2(l0, l1);
}

// Fused split of the 4 weight matrices (blockIdx.y selects). 1 launch instead of 4.
__global__ void split4_kernel(const float* __restrict__ s0, const float* __restrict__ s1,
                              const float* __restrict__ s2, const float* __restrict__ s3,
                              __nv_bfloat16* __restrict__ h0p, __nv_bfloat16* __restrict__ h1p,
                              __nv_bfloat16* __restrict__ h2p, __nv_bfloat16* __restrict__ h3p,
                              __nv_bfloat16* __restrict__ l0p, __nv_bfloat16* __restrict__ l1p,
                              __nv_bfloat16* __restrict__ l2p, __nv_bfloat16* __restrict__ l3p,
                              int n)
{
    const float* src;
    __nv_bfloat16 *hi, *lo;
    switch (blockIdx.y) {
        case 0: src = s0; hi = h0p; lo = l0p; break;
        case 1: src = s1; hi = h1p; lo = l1p; break;
        case 2: src = s2; hi = h2p; lo = l2p; break;
        default: src = s3; hi = h3p; lo = l3p; break;
    }
    int i = (blockIdx.x * blockDim.x + threadIdx.x) * 4;
    if (i >= n) return;
    float4 v = *(const float4*)(src + i);
    uint32_t ha, la, hb, lb;
    pack_split(v.x, v.y, ha, la);
    pack_split(v.z, v.w, hb, lb);
    *(uint2*)(hi + i) = make_uint2(ha, hb);
    *(uint2*)(lo + i) = make_uint2(la, lb);
}

// ---------------------------------------------------------------------------
// bf16-split GEMM via mma.sync — OCCUPANCY-OPTIMIZED (R11 profile: latency-bound
// at occ=20%, tensor=53.8%):
//   CTA tile 128x64, 8 warps (4m x 2n), warp tile 32x32 -> acc 32 regs,
//   __launch_bounds__(256,3) -> 3 CTAs/SM = 24 warps (37.5% occ).
// N-column permutation: warp_n owns cols {16w..16w+15} u {16w+32..16w+47},
// so RoPE pair (j, j+32) = acc tiles (t, t+2) stays register-local.
//   C = Ahi*Whi^T + Alo*Whi^T + Ahi*Wlo^T + bias
// MODE: 0 = fp32+bias; 1 = bias+split; 2 = bias+RoPE+scale+split.
// smem/stage: A 16KB @0, B 8KB @16384; stage stride 24KB; double buffer.
// ---------------------------------------------------------------------------
#define GEMM_SMEM 49152
#define NCHUNK 48

template <int MODE>
__global__ __launch_bounds__(256, 3)
void mma_gemm(const __nv_bfloat16* __restrict__ Ahi, const __nv_bfloat16* __restrict__ Alo,
              const __nv_bfloat16* __restrict__ Whi, const __nv_bfloat16* __restrict__ Wlo,
              const float* __restrict__ bias, float* __restrict__ C,
              __nv_bfloat16* __restrict__ Oh, __nv_bfloat16* __restrict__ Ol,
              int L, int posStride, float scale)
{
    extern __shared__ char smc[];
    const uint32_t sbase = smem_u32(smc);
    const int tid = threadIdx.x;
    const int lane = tid & 31;
    const int wid = tid >> 5;
    const int warp_m = wid & 3;        // 4 warps x 32 rows
    const int warp_n = wid >> 2;       // 2 warps x 32 cols (split-mapped)
    const int m0 = blockIdx.y * 128;
    const int n0 = blockIdx.x * 64;

    const int lc = tid & 7;
    const int lr = tid >> 3;           // 0..31

    float acc[2][4][4];                // [mi][t: g2*2+n8][elem] = 32 regs
#pragma unroll
    for (int mi = 0; mi < 2; mi++)
#pragma unroll
        for (int t = 0; t < 4; t++)
#pragma unroll
            for (int e = 0; e < 4; e++) acc[mi][t][e] = 0.f;

    auto issue_load = [&](int ci) {
        const int seg = ci >> 4;
        const int kk = (ci & 15) << 6;
        const __nv_bfloat16* As = (seg == 1) ? Alo : Ahi;
        const __nv_bfloat16* Ws = (seg == 2) ? Wlo : Whi;
        const uint32_t st = (ci & 1) ? 24576u : 0u;
        const uint32_t da = sbase + st;
        const uint32_t db = sbase + st + 16384u;
        const uint32_t sw = ((uint32_t)(lc ^ (lr & 7))) << 4;
#pragma unroll
        for (int p = 0; p < 4; p++) {   // A: 128 rows
            const int r = lr + p * 32;
            cp16(da + (uint32_t)(r * 128) + sw,
                 As + (size_t)(m0 + r) * DMODEL + kk + lc * 8);
        }
#pragma unroll
        for (int p = 0; p < 2; p++) {   // B: 64 rows
            const int r = lr + p * 32;
            cp16(db + (uint32_t)(r * 128) + sw,
                 Ws + (size_t)(n0 + r) * DMODEL + kk + lc * 8);
        }
    };

    issue_load(0);
    cp_commit();

    for (int i = 0; i < NCHUNK; i++) {
        if (i + 1 < NCHUNK) {
            issue_load(i + 1);
            cp_commit();
            cp_wait1();
        } else {
            cp_wait0();
        }
        __syncthreads();

        const uint32_t st = (i & 1) ? 24576u : 0u;
        const uint32_t abase = sbase + st + (uint32_t)(warp_m * 32) * 128;
        const uint32_t bbase = sbase + st + 16384u;

#pragma unroll
        for (int ks = 0; ks < 4; ks++) {
            uint32_t afr[2][4];
#pragma unroll
            for (int mi = 0; mi < 2; mi++) {
                const int row = mi * 16 + (lane & 15);
                const int ch = ks * 2 + (lane >> 4);
                ldsm_x4(abase + (uint32_t)(row * 128) + (((uint32_t)(ch ^ (row & 7))) << 4),
                        afr[mi]);
            }
#pragma unroll
            for (int g2 = 0; g2 < 2; g2++) {
                // B rows: warp_n*16 + g2*32 + [0..15]
                const int n = warp_n * 16 + g2 * 32 + (lane & 7) + ((lane & 16) >> 1);
                const int ch = ks * 2 + ((lane >> 3) & 1);
                uint32_t bfr[4];
                ldsm_x4(bbase + (uint32_t)(n * 128) + (((uint32_t)(ch ^ (n & 7))) << 4), bfr);
#pragma unroll
                for (int mi = 0; mi < 2; mi++) {
                    mma_bf16(acc[mi][g2 * 2 + 0], afr[mi], bfr[0], bfr[1]);
                    mma_bf16(acc[mi][g2 * 2 + 1], afr[mi], bfr[2], bfr[3]);
                }
            }
        }
        __syncthreads();
    }

    // ---- fused epilogue ----
    // acc tile t -> CTA col offset: warp_n*16 + (t>>1)*32 + (t&1)*8 + (lane&3)*2
    const int cbase = warp_n * 16 + (lane & 3) * 2;

    if (MODE == 0) {
#pragma unroll
        for (int mi = 0; mi < 2; mi++) {
            const int row = m0 + warp_m * 32 + mi * 16 + (lane >> 2);
#pragma unroll
            for (int t = 0; t < 4; t++) {
                const int col = n0 + cbase + (t >> 1) * 32 + (t & 1) * 8;
                const float bx = bias[col], by = bias[col + 1];
                *(float2*)&C[(size_t)row * DMODEL + col] =
                    make_float2(acc[mi][t][0] + bx, acc[mi][t][1] + by);
                *(float2*)&C[(size_t)(row + 8) * DMODEL + col] =
                    make_float2(acc[mi][t][2] + bx, acc[mi][t][3] + by);
            }
        }
    } else if (MODE == 1) {
#pragma unroll
        for (int mi = 0; mi < 2; mi++) {
            const int row = m0 + warp_m * 32 + mi * 16 + (lane >> 2);
#pragma unroll
            for (int t = 0; t < 4; t++) {
                const int col = n0 + cbase + (t >> 1) * 32 + (t & 1) * 8;
                const float bx = bias[col], by = bias[col + 1];
                uint32_t h2, l2;
                pack_split(acc[mi][t][0] + bx, acc[mi][t][1] + by, h2, l2);
                *(uint32_t*)&Oh[(size_t)row * DMODEL + col] = h2;
                *(uint32_t*)&Ol[(size_t)row * DMODEL + col] = l2;
                pack_split(acc[mi][t][2] + bx, acc[mi][t][3] + by, h2, l2);
                *(uint32_t*)&Oh[(size_t)(row + 8) * DMODEL + col] = h2;
                *(uint32_t*)&Ol[(size_t)(row + 8) * DMODEL + col] = l2;
            }
        }
    } else {
        // MODE 2: RoPE pair (j, j+32) = acc tiles (t, t+2), t in {0,1}.
#pragma unroll
        for (int mi = 0; mi < 2; mi++) {
#pragma unroll
            for (int half = 0; half < 2; half++) {
                const int row = m0 + warp_m * 32 + mi * 16 + (lane >> 2) + half * 8;
                const int eo = half * 2;
                const float pos = (float)((row % L) * posStride);
#pragma unroll
                for (int t = 0; t < 2; t++) {
                    const int col = n0 + cbase + t * 8;   // j in 0..31 of this head
                    float y1[2], y2[2];
#pragma unroll
                    for (int el = 0; el < 2; el++) {
                        const int j32 = cbase + t * 8 + el;
                        const float invf =
                            1.0f / powf(10000.0f, (float)j32 * (1.0f / 32.0f));
                        float s, c;
                        sincosf(pos * invf, &s, &c);
                        const float x1 = acc[mi][t][eo + el] + bias[col + el];
                        const float x2 = acc[mi][t + 2][eo + el] + bias[col + 32 + el];
                        y1[el] = (x1 * c - x2 * s) * scale;
                        y2[el] = (x2 * c + x1 * s) * scale;
                    }
                    uint32_t h2, l2;
                    pack_split(y1[0], y1[1], h2, l2);
                    *(uint32_t*)&Oh[(size_t)row * DMODEL + col] = h2;
                    *(uint32_t*)&Ol[(size_t)row * DMODEL + col] = l2;
                    pack_split(y2[0], y2[1], h2, l2);
                    *(uint32_t*)&Oh[(size_t)row * DMODEL + col + 32] = h2;
                    *(uint32_t*)&Ol[(size_t)row * DMODEL + col + 32] = l2;
                }
            }
        }
    }
}

// ---------------------------------------------------------------------------
// Tensor-core flash attention — R8-validated: 2 CTAs/SM, 80KB smem,
// Qlo persistent (re-loaded per chunk), Qhi fragments in regs, 2-stage KV.
// ---------------------------------------------------------------------------
#define ATTN_SMEM 81920
#define NKCH (SK / 64)

__global__ __launch_bounds__(256, 2)
void attn_mma(const __nv_bfloat16* __restrict__ Qh, const __nv_bfloat16* __restrict__ Ql,
              const __nv_bfloat16* __restrict__ Kh, const __nv_bfloat16* __restrict__ Kl,
              const __nv_bfloat16* __restrict__ Vh, const __nv_bfloat16* __restrict__ Vl,
              __nv_bfloat16* __restrict__ Oh, __nv_bfloat16* __restrict__ Ol)
{
    extern __shared__ char smc[];
    const uint32_t sbase = smem_u32(smc);
    const int tid = threadIdx.x;
    const int lane = tid & 31;
    const int wid = tid >> 5;
    const int b = blockIdx.z;
    const int h = blockIdx.y;
    const int s0 = blockIdx.x * 128;

    const uint32_t QLS = 0;
    const uint32_t STG0 = 16384;

    {
        const int r = tid >> 1;
        const int cb = (tid & 1) * 4;
        const size_t src = ((size_t)(b * SQ + s0 + r)) * DMODEL + h * HD;
#pragma unroll
        for (int u = 0; u < 4; u++) {
            const int c = cb + u;
            const uint32_t off = (uint32_t)(r * 128) + (((uint32_t)(c ^ (r & 7))) << 4);
            cp16(sbase + STG0 + off, Qh + src + c * 8);
            cp16(sbase + QLS + off, Ql + src + c * 8);
        }
    }
    cp_commit();
    cp_wait0();
    __syncthreads();

    uint32_t qfh[4][4];
    {
        const int row = wid * 16 + (lane & 15);
#pragma unroll
        for (int ks = 0; ks < 4; ks++) {
            const int ch = ks * 2 + (lane >> 4);
            const uint32_t off = (uint32_t)(row * 128) + (((uint32_t)(ch ^ (row & 7))) << 4);
            ldsm_x4(sbase + STG0 + off, qfh[ks]);
        }
    }
    __syncthreads();

    auto issue_kv = [&](int ci) {
        const uint32_t st = STG0 + (uint32_t)(ci & 1) * 32768u;
        const int r = tid >> 2;
        const int cb = (tid & 3) * 2;
        const size_t src = ((size_t)(b * SK + ci * 64 + r)) * DMODEL + h * HD;
#pragma unroll
        for (int u = 0; u < 2; u++) {
            const int c = cb + u;
            const uint32_t off = (uint32_t)(r * 128) + (((uint32_t)(c ^ (r & 7))) << 4);
            cp16(st + sbase + off, Kh + src + c * 8);
            cp16(st + sbase + 8192u + off, Kl + src + c * 8);
            cp16(st + sbase + 16384u + off, Vh + src + c * 8);
            cp16(st + sbase + 24576u + off, Vl + src + c * 8);
        }
    };

    issue_kv(0);
    cp_commit();

    float oacc[8][4];
#pragma unroll
    for (int g = 0; g < 8; g++)
#pragma unroll
        for (int e = 0; e < 4; e++) oacc[g][e] = 0.f;
    float m0 = -INFINITY, m1 = -INFINITY, l0 = 0.f, l1 = 0.f;

    const int qrow = wid * 16 + (lane & 15);

    for (int i = 0; i < NKCH; i++) {
        if (i + 1 < NKCH) {
            issue_kv(i + 1);
            cp_commit();
            cp_wait1();
        } else {
            cp_wait0();
        }
        __syncthreads();

        const uint32_t st = sbase + STG0 + (uint32_t)(i & 1) * 32768u;
        const uint32_t kh = st, kl = st + 8192u;
        const uint32_t vh = st + 16384u, vl = st + 24576u;

        float sacc[8][4];
#pragma unroll
        for (int g = 0; g < 8; g++)
#pragma unroll
            for (int e = 0; e < 4; e++) sacc[g][e] = 0.f;

#pragma unroll
        for (int ks = 0; ks < 4; ks++) {
            uint32_t qfl[4];
            {
                const int ch = ks * 2 + (lane >> 4);
                const uint32_t off =
                    (uint32_t)(qrow * 128) + (((uint32_t)(ch ^ (qrow & 7))) << 4);
                ldsm_x4(sbase + QLS + off, qfl);
            }
#pragma unroll
            for (int g = 0; g < 4; g++) {
                const int n = g * 16 + (lane & 7) + ((lane & 16) >> 1);
                const int ch = ks * 2 + ((lane >> 3) & 1);
                const uint32_t off = (uint32_t)(n * 128) + (((uint32_t)(ch ^ (n & 7))) << 4);
                uint32_t bh[4], bl[4];
                ldsm_x4(kh + off, bh);
                ldsm_x4(kl + off, bl);
                mma_bf16(sacc[2 * g + 0], qfh[ks], bh[0], bh[1]);
                mma_bf16(sacc[2 * g + 0], qfl, bh[0], bh[1]);
                mma_bf16(sacc[2 * g + 0], qfh[ks], bl[0], bl[1]);
                mma_bf16(sacc[2 * g + 1], qfh[ks], bh[2], bh[3]);
                mma_bf16(sacc[2 * g + 1], qfl, bh[2], bh[3]);
                mma_bf16(sacc[2 * g + 1], qfh[ks], bl[2], bl[3]);
            }
        }

        float mx0 = sacc[0][0], mx1 = sacc[0][2];
#pragma unroll
        for (int g = 0; g < 8; g++) {
            mx0 = fmaxf(mx0, fmaxf(sacc[g][0], sacc[g][1]));
            mx1 = fmaxf(mx1, fmaxf(sacc[g][2], sacc[g][3]));
        }
        mx0 = fmaxf(mx0, __shfl_xor_sync(0xffffffffu, mx0, 1));
        mx0 = fmaxf(mx0, __shfl_xor_sync(0xffffffffu, mx0, 2));
        mx1 = fmaxf(mx1, __shfl_xor_sync(0xffffffffu, mx1, 1));
        mx1 = fmaxf(mx1, __shfl_xor_sync(0xffffffffu, mx1, 2));
        const float mn0 = fmaxf(m0, mx0);
        const float mn1 = fmaxf(m1, mx1);
        const float a0 = fast_exp(m0 - mn0);
        const float a1 = fast_exp(m1 - mn1);
        m0 = mn0; m1 = mn1;
        float s0s = 0.f, s1s = 0.f;
#pragma unroll
        for (int g = 0; g < 8; g++) {
            sacc[g][0] = fast_exp(sacc[g][0] - mn0);
            sacc[g][1] = fast_exp(sacc[g][1] - mn0);
            sacc[g][2] = fast_exp(sacc[g][2] - mn1);
            sacc[g][3] = fast_exp(sacc[g][3] - mn1);
            s0s += sacc[g][0] + sacc[g][1];
            s1s += sacc[g][2] + sacc[g][3];
        }
        l0 = l0 * a0 + s0s;
        l1 = l1 * a1 + s1s;
#pragma unroll
        for (int g = 0; g < 8; g++) {
            oacc[g][0] *= a0; oacc[g][1] *= a0;
            oacc[g][2] *= a1; oacc[g][3] *= a1;
        }

#pragma unroll
        for (int ks = 0; ks < 4; ks++) {
            uint32_t ah[4], al[4];
            pack_split(sacc[2 * ks][0],     sacc[2 * ks][1],     ah[0], al[0]);
            pack_split(sacc[2 * ks][2],     sacc[2 * ks][3],     ah[1], al[1]);
            pack_split(sacc[2 * ks + 1][0], sacc[2 * ks + 1][1], ah[2], al[2]);
            pack_split(sacc[2 * ks + 1][2], sacc[2 * ks + 1][3], ah[3], al[3]);
            const int tile2 = lane >> 3;
            const int key = ks * 16 + (tile2 & 1) * 8 + (lane & 7);
#pragma unroll
            for (int g = 0; g < 4; g++) {
                const int c = g * 2 + (tile2 >> 1);
                const uint32_t off = (uint32_t)(key * 128) + (((uint32_t)(c ^ (key & 7))) << 4);
                uint32_t bh[4], bl[4];
                ldsm_x4t(vh + off, bh);
                ldsm_x4t(vl + off, bl);
                mma_bf16(oacc[2 * g + 0], ah, bh[0], bh[1]);
                mma_bf16(oacc[2 * g + 0], al, bh[0], bh[1]);
                mma_bf16(oacc[2 * g + 0], ah, bl[0], bl[1]);
                mma_bf16(oacc[2 * g + 1], ah, bh[2], bh[3]);
                mma_bf16(oacc[2 * g + 1], al, bh[2], bh[3]);
                mma_bf16(oacc[2 * g + 1], ah, bl[2], bl[3]);
            }
        }
        __syncthreads();
    }

    l0 += __shfl_xor_sync(0xffffffffu, l0, 1);
    l0 += __shfl_xor_sync(0xffffffffu, l0, 2);
    l1 += __shfl_xor_sync(0xffffffffu, l1, 1);
    l1 += __shfl_xor_sync(0xffffffffu, l1, 2);
    const float inv0 = 1.0f / l0;
    const float inv1 = 1.0f / l1;
    const int r0 = s0 + wid * 16 + (lane >> 2);
#pragma unroll
    for (int g = 0; g < 8; g++) {
        const int col = h * HD + g * 8 + (lane & 3) * 2;
        uint32_t h2, l2;
        pack_split(oacc[g][0] * inv0, oacc[g][1] * inv0, h2, l2);
        *(uint32_t*)&Oh[((size_t)(b * SQ) + r0) * DMODEL + col] = h2;
        *(uint32_t*)&Ol[((size_t)(b * SQ) + r0) * DMODEL + col] = l2;
        pack_split(oacc[g][2] * inv1, oacc[g][3] * inv1, h2, l2);
        *(uint32_t*)&Oh[((size_t)(b * SQ) + r0 + 8) * DMODEL + col] = h2;
        *(uint32_t*)&Ol[((size_t)(b * SQ) + r0 + 8) * DMODEL + col] = l2;
    }
}

// ---------------------------------------------------------------------------
extern "C" void kernel_launch(void* const* d_in, const int* in_sizes, int n_in,
                              void* d_out, int out_size)
{
    const float* query = (const float*)d_in[0];
    const float* kv    = (const float*)d_in[1];
    const float* q_w   = (const float*)d_in[2];
    const float* q_b   = (const float*)d_in[3];
    const float* k_w   = (const float*)d_in[4];
    const float* k_b   = (const float*)d_in[5];
    const float* v_w   = (const float*)d_in[6];
    const float* v_b   = (const float*)d_in[7];
    const float* out_w = (const float*)d_in[8];
    const float* out_b = (const float*)d_in[9];
    float* out = (float*)d_out;

    __nv_bfloat16 *qh, *ql, *kvh, *kvl, *oh, *ol;
    __nv_bfloat16 *wqh, *wql, *wkh, *wkl, *wvh, *wvl, *woh, *wol;
    __nv_bfloat16 *aqh, *aql, *akh, *akl, *avh, *avl;
    cudaGetSymbolAddress((void**)&qh,  g_qh);  cudaGetSymbolAddress((void**)&ql,  g_ql);
    cudaGetSymbolAddress((void**)&kvh, g_kvh); cudaGetSymbolAddress((void**)&kvl, g_kvl);
    cudaGetSymbolAddress((void**)&oh,  g_oh);  cudaGetSymbolAddress((void**)&ol,  g_ol);
    cudaGetSymbolAddress((void**)&wqh, g_wqh); cudaGetSymbolAddress((void**)&wql, g_wql);
    cudaGetSymbolAddress((void**)&wkh, g_wkh); cudaGetSymbolAddress((void**)&wkl, g_wkl);
    cudaGetSymbolAddress((void**)&wvh, g_wvh); cudaGetSymbolAddress((void**)&wvl, g_wvl);
    cudaGetSymbolAddress((void**)&woh, g_woh); cudaGetSymbolAddress((void**)&wol, g_wol);
    cudaGetSymbolAddress((void**)&aqh, g_aqh); cudaGetSymbolAddress((void**)&aql, g_aql);
    cudaGetSymbolAddress((void**)&akh, g_akh); cudaGetSymbolAddress((void**)&akl, g_akl);
    cudaGetSymbolAddress((void**)&avh, g_avh); cudaGetSymbolAddress((void**)&avl, g_avl);

    const int NQ = NB * SQ * DMODEL;
    const int NK = NB * SK * DMODEL;
    const int NW = DMODEL * DMODEL;

    // launch 0: all 4 weight splits fused; launch 1-2: input splits
    split4_kernel<<<dim3(NW / 1024, 4), 256>>>(q_w, k_w, v_w, out_w,
                                               wqh, wkh, wvh, woh,
                                               wql, wkl, wvl, wol, NW);
    split_kernel<<<NQ / 1024, 256>>>(query, qh, ql, NQ);
    split_kernel<<<NK / 1024, 256>>>(kv, kvh, kvl, NK);

    // launches 3-5: projections (launch 5 = V-proj -> captured by ncu -s 5 -c 1)
    cudaFuncSetAttribute(mma_gemm<0>, cudaFuncAttributeMaxDynamicSharedMemorySize, GEMM_SMEM);
    cudaFuncSetAttribute(mma_gemm<1>, cudaFuncAttributeMaxDynamicSharedMemorySize, GEMM_SMEM);
    cudaFuncSetAttribute(mma_gemm<2>, cudaFuncAttributeMaxDynamicSharedMemorySize, GEMM_SMEM);
    mma_gemm<2><<<dim3(16, 32), 256, GEMM_SMEM>>>(qh, ql, wqh, wql, q_b, nullptr,
                                                  aqh, aql, SQ, 2, 0.125f);
    mma_gemm<2><<<dim3(16, 64), 256, GEMM_SMEM>>>(kvh, kvl, wkh, wkl, k_b, nullptr,
                                                  akh, akl, SK, 1, 1.0f);
    mma_gemm<1><<<dim3(16, 64), 256, GEMM_SMEM>>>(kvh, kvl, wvh, wvl, v_b, nullptr,
                                                  avh, avl, 0, 0, 0.f);

    // tensor-core flash attention, bf16-split output
    cudaFuncSetAttribute(attn_mma, cudaFuncAttributeMaxDynamicSharedMemorySize, ATTN_SMEM);
    attn_mma<<<dim3(SQ / 128, NHEAD, NB), 256, ATTN_SMEM>>>(aqh, aql, akh, akl, avh, avl, oh, ol);

    // output projection (fp32 out)
    mma_gemm<0><<<dim3(16, 32), 256, GEMM_SMEM>>>(oh, ol, woh, wol, out_b, out,
                                                  nullptr, nullptr, 0, 0, 0.f);
}

// round 13
// speedup vs baseline: 1.0100x; 1.0100x over previous
#include <cuda_runtime.h>
#include <cuda_bf16.h>
#include <math.h>
#include <stdint.h>

#define DMODEL 1024
#define NHEAD  16
#define HD     64
#define NB     4
#define SQ     1024
#define SK     2048

// ---------------------------------------------------------------------------
// Scratch (__device__ globals: allocation-free rule)
// ---------------------------------------------------------------------------
__device__ __nv_bfloat16 g_qh[NB * SQ * DMODEL];
__device__ __nv_bfloat16 g_ql[NB * SQ * DMODEL];
__device__ __nv_bfloat16 g_kvh[NB * SK * DMODEL];
__device__ __nv_bfloat16 g_kvl[NB * SK * DMODEL];
__device__ __nv_bfloat16 g_oh[NB * SQ * DMODEL];
__device__ __nv_bfloat16 g_ol[NB * SQ * DMODEL];
__device__ __nv_bfloat16 g_wqh[DMODEL * DMODEL];
__device__ __nv_bfloat16 g_wql[DMODEL * DMODEL];
__device__ __nv_bfloat16 g_wkh[DMODEL * DMODEL];
__device__ __nv_bfloat16 g_wkl[DMODEL * DMODEL];
__device__ __nv_bfloat16 g_wvh[DMODEL * DMODEL];
__device__ __nv_bfloat16 g_wvl[DMODEL * DMODEL];
__device__ __nv_bfloat16 g_woh[DMODEL * DMODEL];
__device__ __nv_bfloat16 g_wol[DMODEL * DMODEL];

// attention operands (bf16 hi/lo, post-RoPE, written by fused gemm epilogues)
__device__ __nv_bfloat16 g_aqh[NB * SQ * DMODEL];
__device__ __nv_bfloat16 g_aql[NB * SQ * DMODEL];
__device__ __nv_bfloat16 g_akh[NB * SK * DMODEL];
__device__ __nv_bfloat16 g_akl[NB * SK * DMODEL];
__device__ __nv_bfloat16 g_avh[NB * SK * DMODEL];
__device__ __nv_bfloat16 g_avl[NB * SK * DMODEL];

// ---------------------------------------------------------------------------
// Helpers
// ---------------------------------------------------------------------------
__device__ __forceinline__ uint32_t smem_u32(const void* p) {
    uint32_t a;
    asm("{ .reg .u64 t; cvta.to.shared.u64 t, %1; cvt.u32.u64 %0, t; }" : "=r"(a) : "l"(p));
    return a;
}
__device__ __forceinline__ void cp16(uint32_t dst, const void* src) {
    asm volatile("cp.async.cg.shared.global [%0], [%1], 16;" :: "r"(dst), "l"(src));
}
__device__ __forceinline__ void cp_commit() {
    asm volatile("cp.async.commit_group;" ::: "memory");
}
__device__ __forceinline__ void cp_wait1() {
    asm volatile("cp.async.wait_group 1;" ::: "memory");
}
__device__ __forceinline__ void cp_wait0() {
    asm volatile("cp.async.wait_group 0;" ::: "memory");
}
__device__ __forceinline__ void ldsm_x4(uint32_t addr, uint32_t* r) {
    asm volatile("ldmatrix.sync.aligned.m8n8.x4.shared.b16 {%0,%1,%2,%3}, [%4];"
                 : "=r"(r[0]), "=r"(r[1]), "=r"(r[2]), "=r"(r[3]) : "r"(addr));
}
__device__ __forceinline__ void ldsm_x4t(uint32_t addr, uint32_t* r) {
    asm volatile("ldmatrix.sync.aligned.m8n8.x4.trans.shared.b16 {%0,%1,%2,%3}, [%4];"
                 : "=r"(r[0]), "=r"(r[1]), "=r"(r[2]), "=r"(r[3]) : "r"(addr));
}
__device__ __forceinline__ void mma_bf16(float* d, const uint32_t* a, uint32_t b0, uint32_t b1) {
    asm volatile(
        "mma.sync.aligned.m16n8k16.row.col.f32.bf16.bf16.f32 "
        "{%0,%1,%2,%3}, {%4,%5,%6,%7}, {%8,%9}, {%0,%1,%2,%3};"
        : "+f"(d[0]), "+f"(d[1]), "+f"(d[2]), "+f"(d[3])
        : "r"(a[0]), "r"(a[1]), "r"(a[2]), "r"(a[3]), "r"(b0), "r"(b1));
}
// exp on the FMA pipe: 2^(x*log2e), deg-5 poly. rel err ~5e-7.
__device__ __forceinline__ float fast_exp(float x) {
    float y = fmaxf(x * 1.4426950408889634f, -100.0f);
    int n = __float2int_rn(y);
    float f = y - (float)n;
    float p = 1.3333558146e-3f;
    p = fmaf(p, f, 9.6181291076e-3f);
    p = fmaf(p, f, 5.5504108665e-2f);
    p = fmaf(p, f, 2.4022650696e-1f);
    p = fmaf(p, f, 6.9314718056e-1f);
    p = fmaf(p, f, 1.0f);
    return __int_as_float(__float_as_int(p) + (n << 23));
}
// split (a,b) fp32 pair -> bf16x2 hi + bf16x2 lo (lo = residual)
__device__ __forceinline__ void pack_split(float a, float b, uint32_t& hi2, uint32_t& lo2) {
    __nv_bfloat162 hb = __float22bfloat162_rn(make_float2(a, b));
    uint32_t h;
    memcpy(&h, &hb, 4);
    float ra = a - __uint_as_float(h << 16);
    float rb = b - __uint_as_float(h & 0xFFFF0000u);
    __nv_bfloat162 lb = __float22bfloat162_rn(make_float2(ra, rb));
    uint32_t l;
    memcpy(&l, &lb, 4);
    hi2 = h; lo2 = l;
}

// ---------------------------------------------------------------------------
// Fused split of the 4 weight matrices (blockIdx.y selects). 1 launch.
// ---------------------------------------------------------------------------
__global__ void split4_kernel(const float* __restrict__ s0, const float* __restrict__ s1,
                              const float* __restrict__ s2, const float* __restrict__ s3,
                              __nv_bfloat16* __restrict__ h0p, __nv_bfloat16* __restrict__ h1p,
                              __nv_bfloat16* __restrict__ h2p, __nv_bfloat16* __restrict__ h3p,
                              __nv_bfloat16* __restrict__ l0p, __nv_bfloat16* __restrict__ l1p,
                              __nv_bfloat16* __restrict__ l2p, __nv_bfloat16* __restrict__ l3p,
                              int n)
{
    const float* src;
    __nv_bfloat16 *hi, *lo;
    switch (blockIdx.y) {
        case 0: src = s0; hi = h0p; lo = l0p; break;
        case 1: src = s1; hi = h1p; lo = l1p; break;
        case 2: src = s2; hi = h2p; lo = l2p; break;
        default: src = s3; hi = h3p; lo = l3p; break;
    }
    int i = (blockIdx.x * blockDim.x + threadIdx.x) * 4;
    if (i >= n) return;
    float4 v = *(const float4*)(src + i);
    uint32_t ha, la, hb, lb;
    pack_split(v.x, v.y, ha, la);
    pack_split(v.z, v.w, hb, lb);
    *(uint2*)(hi + i) = make_uint2(ha, hb);
    *(uint2*)(lo + i) = make_uint2(la, lb);
}

// Fused split of query + kv inputs (blockIdx.y selects). 1 launch.
__global__ void split2_kernel(const float* __restrict__ q, const float* __restrict__ kvp,
                              __nv_bfloat16* __restrict__ qh, __nv_bfloat16* __restrict__ ql,
                              __nv_bfloat16* __restrict__ kvh, __nv_bfloat16* __restrict__ kvl,
                              int nq, int nk)
{
    const float* src;
    __nv_bfloat16 *hi, *lo;
    int n;
    if (blockIdx.y == 0) { src = q; hi = qh; lo = ql; n = nq; }
    else                 { src = kvp; hi = kvh; lo = kvl; n = nk; }
    int i = (blockIdx.x * blockDim.x + threadIdx.x) * 4;
    if (i >= n) return;
    float4 v = *(const float4*)(src + i);
    uint32_t ha, la, hb, lb;
    pack_split(v.x, v.y, ha, la);
    pack_split(v.z, v.w, hb, lb);
    *(uint2*)(hi + i) = make_uint2(ha, hb);
    *(uint2*)(lo + i) = make_uint2(la, lb);
}

// ---------------------------------------------------------------------------
// bf16-split GEMM via mma.sync — EXACT R11 config (best measured: 841.7us,
// tensor=53.8%; R12's occupancy experiment regressed -> this is the optimum):
//   C = Ahi*Whi^T + Alo*Whi^T + Ahi*Wlo^T + bias
// 128x128 CTA tile, BK=64, 48 chunks (3 segments x 16), double buffer.
// MODE: 0 = fp32+bias; 1 = bias+split; 2 = bias+RoPE+scale+split.
// ---------------------------------------------------------------------------
#define GEMM_SMEM 65536
#define NCHUNK 48

template <int MODE>
__global__ __launch_bounds__(256, 2)
void mma_gemm(const __nv_bfloat16* __restrict__ Ahi, const __nv_bfloat16* __restrict__ Alo,
              const __nv_bfloat16* __restrict__ Whi, const __nv_bfloat16* __restrict__ Wlo,
              const float* __restrict__ bias, float* __restrict__ C,
              __nv_bfloat16* __restrict__ Oh, __nv_bfloat16* __restrict__ Ol,
              int L, int posStride, float scale)
{
    extern __shared__ char smc[];
    const uint32_t sbase = smem_u32(smc);
    const int tid = threadIdx.x;
    const int lane = tid & 31;
    const int wid = tid >> 5;
    const int warp_m = wid & 3;
    const int warp_n = wid >> 2;
    const int m0 = blockIdx.y * 128;
    const int n0 = blockIdx.x * 128;

    const int lc = tid & 7;
    const int lr = tid >> 3;

    float acc[2][8][4];
#pragma unroll
    for (int mi = 0; mi < 2; mi++)
#pragma unroll
        for (int ni = 0; ni < 8; ni++)
#pragma unroll
            for (int e = 0; e < 4; e++) acc[mi][ni][e] = 0.f;

    auto issue_load = [&](int ci) {
        const int seg = ci >> 4;
        const int kk = (ci & 15) << 6;
        const __nv_bfloat16* As = (seg == 1) ? Alo : Ahi;
        const __nv_bfloat16* Ws = (seg == 2) ? Wlo : Whi;
        const uint32_t aoff = (ci & 1) ? 32768u : 0u;
        const uint32_t da = sbase + aoff;
        const uint32_t db = sbase + aoff + 16384u;
        const uint32_t sw = ((uint32_t)(lc ^ (lr & 7))) << 4;
#pragma unroll
        for (int p = 0; p < 4; p++) {
            const int r = lr + p * 32;
            const uint32_t so = (uint32_t)(r * 128) + sw;
            cp16(da + so, As + (size_t)(m0 + r) * DMODEL + kk + lc * 8);
            cp16(db + so, Ws + (size_t)(n0 + r) * DMODEL + kk + lc * 8);
        }
    };

    issue_load(0);
    cp_commit();

    for (int i = 0; i < NCHUNK; i++) {
        if (i + 1 < NCHUNK) {
            issue_load(i + 1);
            cp_commit();
            cp_wait1();
        } else {
            cp_wait0();
        }
        __syncthreads();

        const uint32_t aoff = (i & 1) ? 32768u : 0u;
        const uint32_t abase = sbase + aoff + (uint32_t)(warp_m * 32) * 128;
        const uint32_t bbase = sbase + aoff + 16384u + (uint32_t)(warp_n * 64) * 128;

#pragma unroll
        for (int ks = 0; ks < 4; ks++) {
            uint32_t afr[2][4];
#pragma unroll
            for (int mi = 0; mi < 2; mi++) {
                const int row = mi * 16 + (lane & 15);
                const int ch = ks * 2 + (lane >> 4);
                ldsm_x4(abase + (uint32_t)(row * 128) + (((uint32_t)(ch ^ (row & 7))) << 4),
                        afr[mi]);
            }
#pragma unroll
            for (int g = 0; g < 4; g++) {
                const int n = g * 16 + (lane & 7) + ((lane & 16) >> 1);
                const int ch = ks * 2 + ((lane >> 3) & 1);
                uint32_t bfr[4];
                ldsm_x4(bbase + (uint32_t)(n * 128) + (((uint32_t)(ch ^ (n & 7))) << 4), bfr);
#pragma unroll
                for (int mi = 0; mi < 2; mi++) {
                    mma_bf16(acc[mi][2 * g + 0], afr[mi], bfr[0], bfr[1]);
                    mma_bf16(acc[mi][2 * g + 1], afr[mi], bfr[2], bfr[3]);
                }
            }
        }
        __syncthreads();
    }

    // ---- fused epilogue ----
    const int colb = n0 + warp_n * 64 + (lane & 3) * 2;

    if (MODE == 0) {
#pragma unroll
        for (int mi = 0; mi < 2; mi++) {
            const int row = m0 + warp_m * 32 + mi * 16 + (lane >> 2);
#pragma unroll
            for (int ni = 0; ni < 8; ni++) {
                const int col = colb + ni * 8;
                const float bx = bias[col], by = bias[col + 1];
                *(float2*)&C[(size_t)row * DMODEL + col] =
                    make_float2(acc[mi][ni][0] + bx, acc[mi][ni][1] + by);
                *(float2*)&C[(size_t)(row + 8) * DMODEL + col] =
                    make_float2(acc[mi][ni][2] + bx, acc[mi][ni][3] + by);
            }
        }
    } else if (MODE == 1) {
#pragma unroll
        for (int mi = 0; mi < 2; mi++) {
            const int row = m0 + warp_m * 32 + mi * 16 + (lane >> 2);
#pragma unroll
            for (int ni = 0; ni < 8; ni++) {
                const int col = colb + ni * 8;
                const float bx = bias[col], by = bias[col + 1];
                uint32_t h2, l2;
                pack_split(acc[mi][ni][0] + bx, acc[mi][ni][1] + by, h2, l2);
                *(uint32_t*)&Oh[(size_t)row * DMODEL + col] = h2;
                *(uint32_t*)&Ol[(size_t)row * DMODEL + col] = l2;
                pack_split(acc[mi][ni][2] + bx, acc[mi][ni][3] + by, h2, l2);
                *(uint32_t*)&Oh[(size_t)(row + 8) * DMODEL + col] = h2;
                *(uint32_t*)&Ol[(size_t)(row + 8) * DMODEL + col] = l2;
            }
        }
    } else {
        // MODE 2: RoPE pairs (j, j+32) are (ni, ni+4) — register-local.
#pragma unroll
        for (int mi = 0; mi < 2; mi++) {
#pragma unroll
            for (int half = 0; half < 2; half++) {
                const int row = m0 + warp_m * 32 + mi * 16 + (lane >> 2) + half * 8;
                const int eo = half * 2;
                const float pos = (float)((row % L) * posStride);
#pragma unroll
                for (int nj = 0; nj < 4; nj++) {
                    const int col = colb + nj * 8;
                    float y1[2], y2[2];
#pragma unroll
                    for (int el = 0; el < 2; el++) {
                        const int j32 = nj * 8 + (lane & 3) * 2 + el;
                        const float invf =
                            1.0f / powf(10000.0f, (float)j32 * (1.0f / 32.0f));
                        float s, c;
                        sincosf(pos * invf, &s, &c);
                        const float x1 = acc[mi][nj][eo + el] + bias[col + el];
                        const float x2 = acc[mi][nj + 4][eo + el] + bias[col + 32 + el];
                        y1[el] = (x1 * c - x2 * s) * scale;
                        y2[el] = (x2 * c + x1 * s) * scale;
                    }
                    uint32_t h2, l2;
                    pack_split(y1[0], y1[1], h2, l2);
                    *(uint32_t*)&Oh[(size_t)row * DMODEL + col] = h2;
                    *(uint32_t*)&Ol[(size_t)row * DMODEL + col] = l2;
                    pack_split(y2[0], y2[1], h2, l2);
                    *(uint32_t*)&Oh[(size_t)row * DMODEL + col + 32] = h2;
                    *(uint32_t*)&Ol[(size_t)row * DMODEL + col + 32] = l2;
                }
            }
        }
    }
}

// ---------------------------------------------------------------------------
// Tensor-core flash attention — R8-validated config (launch #5 -> ncu target).
// ---------------------------------------------------------------------------
#define ATTN_SMEM 81920
#define NKCH (SK / 64)

__global__ __launch_bounds__(256, 2)
void attn_mma(const __nv_bfloat16* __restrict__ Qh, const __nv_bfloat16* __restrict__ Ql,
              const __nv_bfloat16* __restrict__ Kh, const __nv_bfloat16* __restrict__ Kl,
              const __nv_bfloat16* __restrict__ Vh, const __nv_bfloat16* __restrict__ Vl,
              __nv_bfloat16* __restrict__ Oh, __nv_bfloat16* __restrict__ Ol)
{
    extern __shared__ char smc[];
    const uint32_t sbase = smem_u32(smc);
    const int tid = threadIdx.x;
    const int lane = tid & 31;
    const int wid = tid >> 5;
    const int b = blockIdx.z;
    const int h = blockIdx.y;
    const int s0 = blockIdx.x * 128;

    const uint32_t QLS = 0;
    const uint32_t STG0 = 16384;

    {
        const int r = tid >> 1;
        const int cb = (tid & 1) * 4;
        const size_t src = ((size_t)(b * SQ + s0 + r)) * DMODEL + h * HD;
#pragma unroll
        for (int u = 0; u < 4; u++) {
            const int c = cb + u;
            const uint32_t off = (uint32_t)(r * 128) + (((uint32_t)(c ^ (r & 7))) << 4);
            cp16(sbase + STG0 + off, Qh + src + c * 8);
            cp16(sbase + QLS + off, Ql + src + c * 8);
        }
    }
    cp_commit();
    cp_wait0();
    __syncthreads();

    uint32_t qfh[4][4];
    {
        const int row = wid * 16 + (lane & 15);
#pragma unroll
        for (int ks = 0; ks < 4; ks++) {
            const int ch = ks * 2 + (lane >> 4);
            const uint32_t off = (uint32_t)(row * 128) + (((uint32_t)(ch ^ (row & 7))) << 4);
            ldsm_x4(sbase + STG0 + off, qfh[ks]);
        }
    }
    __syncthreads();

    auto issue_kv = [&](int ci) {
        const uint32_t st = STG0 + (uint32_t)(ci & 1) * 32768u;
        const int r = tid >> 2;
        const int cb = (tid & 3) * 2;
        const size_t src = ((size_t)(b * SK + ci * 64 + r)) * DMODEL + h * HD;
#pragma unroll
        for (int u = 0; u < 2; u++) {
            const int c = cb + u;
            const uint32_t off = (uint32_t)(r * 128) + (((uint32_t)(c ^ (r & 7))) << 4);
            cp16(st + sbase + off, Kh + src + c * 8);
            cp16(st + sbase + 8192u + off, Kl + src + c * 8);
            cp16(st + sbase + 16384u + off, Vh + src + c * 8);
            cp16(st + sbase + 24576u + off, Vl + src + c * 8);
        }
    };

    issue_kv(0);
    cp_commit();

    float oacc[8][4];
#pragma unroll
    for (int g = 0; g < 8; g++)
#pragma unroll
        for (int e = 0; e < 4; e++) oacc[g][e] = 0.f;
    float m0 = -INFINITY, m1 = -INFINITY, l0 = 0.f, l1 = 0.f;

    const int qrow = wid * 16 + (lane & 15);

    for (int i = 0; i < NKCH; i++) {
        if (i + 1 < NKCH) {
            issue_kv(i + 1);
            cp_commit();
            cp_wait1();
        } else {
            cp_wait0();
        }
        __syncthreads();

        const uint32_t st = sbase + STG0 + (uint32_t)(i & 1) * 32768u;
        const uint32_t kh = st, kl = st + 8192u;
        const uint32_t vh = st + 16384u, vl = st + 24576u;

        float sacc[8][4];
#pragma unroll
        for (int g = 0; g < 8; g++)
#pragma unroll
            for (int e = 0; e < 4; e++) sacc[g][e] = 0.f;

#pragma unroll
        for (int ks = 0; ks < 4; ks++) {
            uint32_t qfl[4];
            {
                const int ch = ks * 2 + (lane >> 4);
                const uint32_t off =
                    (uint32_t)(qrow * 128) + (((uint32_t)(ch ^ (qrow & 7))) << 4);
                ldsm_x4(sbase + QLS + off, qfl);
            }
#pragma unroll
            for (int g = 0; g < 4; g++) {
                const int n = g * 16 + (lane & 7) + ((lane & 16) >> 1);
                const int ch = ks * 2 + ((lane >> 3) & 1);
                const uint32_t off = (uint32_t)(n * 128) + (((uint32_t)(ch ^ (n & 7))) << 4);
                uint32_t bh[4], bl[4];
                ldsm_x4(kh + off, bh);
                ldsm_x4(kl + off, bl);
                mma_bf16(sacc[2 * g + 0], qfh[ks], bh[0], bh[1]);
                mma_bf16(sacc[2 * g + 0], qfl, bh[0], bh[1]);
                mma_bf16(sacc[2 * g + 0], qfh[ks], bl[0], bl[1]);
                mma_bf16(sacc[2 * g + 1], qfh[ks], bh[2], bh[3]);
                mma_bf16(sacc[2 * g + 1], qfl, bh[2], bh[3]);
                mma_bf16(sacc[2 * g + 1], qfh[ks], bl[2], bl[3]);
            }
        }

        float mx0 = sacc[0][0], mx1 = sacc[0][2];
#pragma unroll
        for (int g = 0; g < 8; g++) {
            mx0 = fmaxf(mx0, fmaxf(sacc[g][0], sacc[g][1]));
            mx1 = fmaxf(mx1, fmaxf(sacc[g][2], sacc[g][3]));
        }
        mx0 = fmaxf(mx0, __shfl_xor_sync(0xffffffffu, mx0, 1));
        mx0 = fmaxf(mx0, __shfl_xor_sync(0xffffffffu, mx0, 2));
        mx1 = fmaxf(mx1, __shfl_xor_sync(0xffffffffu, mx1, 1));
        mx1 = fmaxf(mx1, __shfl_xor_sync(0xffffffffu, mx1, 2));
        const float mn0 = fmaxf(m0, mx0);
        const float mn1 = fmaxf(m1, mx1);
        const float a0 = fast_exp(m0 - mn0);
        const float a1 = fast_exp(m1 - mn1);
        m0 = mn0; m1 = mn1;
        float s0s = 0.f, s1s = 0.f;
#pragma unroll
        for (int g = 0; g < 8; g++) {
            sacc[g][0] = fast_exp(sacc[g][0] - mn0);
            sacc[g][1] = fast_exp(sacc[g][1] - mn0);
            sacc[g][2] = fast_exp(sacc[g][2] - mn1);
            sacc[g][3] = fast_exp(sacc[g][3] - mn1);
            s0s += sacc[g][0] + sacc[g][1];
            s1s += sacc[g][2] + sacc[g][3];
        }
        l0 = l0 * a0 + s0s;
        l1 = l1 * a1 + s1s;
#pragma unroll
        for (int g = 0; g < 8; g++) {
            oacc[g][0] *= a0; oacc[g][1] *= a0;
            oacc[g][2] *= a1; oacc[g][3] *= a1;
        }

#pragma unroll
        for (int ks = 0; ks < 4; ks++) {
            uint32_t ah[4], al[4];
            pack_split(sacc[2 * ks][0],     sacc[2 * ks][1],     ah[0], al[0]);
            pack_split(sacc[2 * ks][2],     sacc[2 * ks][3],     ah[1], al[1]);
            pack_split(sacc[2 * ks + 1][0], sacc[2 * ks + 1][1], ah[2], al[2]);
            pack_split(sacc[2 * ks + 1][2], sacc[2 * ks + 1][3], ah[3], al[3]);
            const int tile2 = lane >> 3;
            const int key = ks * 16 + (tile2 & 1) * 8 + (lane & 7);
#pragma unroll
            for (int g = 0; g < 4; g++) {
                const int c = g * 2 + (tile2 >> 1);
                const uint32_t off = (uint32_t)(key * 128) + (((uint32_t)(c ^ (key & 7))) << 4);
                uint32_t bh[4], bl[4];
                ldsm_x4t(vh + off, bh);
                ldsm_x4t(vl + off, bl);
                mma_bf16(oacc[2 * g + 0], ah, bh[0], bh[1]);
                mma_bf16(oacc[2 * g + 0], al, bh[0], bh[1]);
                mma_bf16(oacc[2 * g + 0], ah, bl[0], bl[1]);
                mma_bf16(oacc[2 * g + 1], ah, bh[2], bh[3]);
                mma_bf16(oacc[2 * g + 1], al, bh[2], bh[3]);
                mma_bf16(oacc[2 * g + 1], ah, bl[2], bl[3]);
            }
        }
        __syncthreads();
    }

    l0 += __shfl_xor_sync(0xffffffffu, l0, 1);
    l0 += __shfl_xor_sync(0xffffffffu, l0, 2);
    l1 += __shfl_xor_sync(0xffffffffu, l1, 1);
    l1 += __shfl_xor_sync(0xffffffffu, l1, 2);
    const float inv0 = 1.0f / l0;
    const float inv1 = 1.0f / l1;
    const int r0 = s0 + wid * 16 + (lane >> 2);
#pragma unroll
    for (int g = 0; g < 8; g++) {
        const int col = h * HD + g * 8 + (lane & 3) * 2;
        uint32_t h2, l2;
        pack_split(oacc[g][0] * inv0, oacc[g][1] * inv0, h2, l2);
        *(uint32_t*)&Oh[((size_t)(b * SQ) + r0) * DMODEL + col] = h2;
        *(uint32_t*)&Ol[((size_t)(b * SQ) + r0) * DMODEL + col] = l2;
        pack_split(oacc[g][2] * inv1, oacc[g][3] * inv1, h2, l2);
        *(uint32_t*)&Oh[((size_t)(b * SQ) + r0 + 8) * DMODEL + col] = h2;
        *(uint32_t*)&Ol[((size_t)(b * SQ) + r0 + 8) * DMODEL + col] = l2;
    }
}

// ---------------------------------------------------------------------------
extern "C" void kernel_launch(void* const* d_in, const int* in_sizes, int n_in,
                              void* d_out, int out_size)
{
    const float* query = (const float*)d_in[0];
    const float* kv    = (const float*)d_in[1];
    const float* q_w   = (const float*)d_in[2];
    const float* q_b   = (const float*)d_in[3];
    const float* k_w   = (const float*)d_in[4];
    const float* k_b   = (const float*)d_in[5];
    const float* v_w   = (const float*)d_in[6];
    const float* v_b   = (const float*)d_in[7];
    const float* out_w = (const float*)d_in[8];
    const float* out_b = (const float*)d_in[9];
    float* out = (float*)d_out;

    __nv_bfloat16 *qh, *ql, *kvh, *kvl, *oh, *ol;
    __nv_bfloat16 *wqh, *wql, *wkh, *wkl, *wvh, *wvl, *woh, *wol;
    __nv_bfloat16 *aqh, *aql, *akh, *akl, *avh, *avl;
    cudaGetSymbolAddress((void**)&qh,  g_qh);  cudaGetSymbolAddress((void**)&ql,  g_ql);
    cudaGetSymbolAddress((void**)&kvh, g_kvh); cudaGetSymbolAddress((void**)&kvl, g_kvl);
    cudaGetSymbolAddress((void**)&oh,  g_oh);  cudaGetSymbolAddress((void**)&ol,  g_ol);
    cudaGetSymbolAddress((void**)&wqh, g_wqh); cudaGetSymbolAddress((void**)&wql, g_wql);
    cudaGetSymbolAddress((void**)&wkh, g_wkh); cudaGetSymbolAddress((void**)&wkl, g_wkl);
    cudaGetSymbolAddress((void**)&wvh, g_wvh); cudaGetSymbolAddress((void**)&wvl, g_wvl);
    cudaGetSymbolAddress((void**)&woh, g_woh); cudaGetSymbolAddress((void**)&wol, g_wol);
    cudaGetSymbolAddress((void**)&aqh, g_aqh); cudaGetSymbolAddress((void**)&aql, g_aql);
    cudaGetSymbolAddress((void**)&akh, g_akh); cudaGetSymbolAddress((void**)&akl, g_akl);
    cudaGetSymbolAddress((void**)&avh, g_avh); cudaGetSymbolAddress((void**)&avl, g_avl);

    const int NQ = NB * SQ * DMODEL;
    const int NK = NB * SK * DMODEL;
    const int NW = DMODEL * DMODEL;

    // launch 0: weight splits; launch 1: input splits (fused q+kv)
    split4_kernel<<<dim3(NW / 1024, 4), 256>>>(q_w, k_w, v_w, out_w,
                                               wqh, wkh, wvh, woh,
                                               wql, wkl, wvl, wol, NW);
    split2_kernel<<<dim3(NK / 1024, 2), 256>>>(query, kv, qh, ql, kvh, kvl, NQ, NK);

    // launches 2-4: projections
    cudaFuncSetAttribute(mma_gemm<0>, cudaFuncAttributeMaxDynamicSharedMemorySize, GEMM_SMEM);
    cudaFuncSetAttribute(mma_gemm<1>, cudaFuncAttributeMaxDynamicSharedMemorySize, GEMM_SMEM);
    cudaFuncSetAttribute(mma_gemm<2>, cudaFuncAttributeMaxDynamicSharedMemorySize, GEMM_SMEM);
    mma_gemm<2><<<dim3(8, 32), 256, GEMM_SMEM>>>(qh, ql, wqh, wql, q_b, nullptr,
                                                 aqh, aql, SQ, 2, 0.125f);
    mma_gemm<2><<<dim3(8, 64), 256, GEMM_SMEM>>>(kvh, kvl, wkh, wkl, k_b, nullptr,
                                                 akh, akl, SK, 1, 1.0f);
    mma_gemm<1><<<dim3(8, 64), 256, GEMM_SMEM>>>(kvh, kvl, wvh, wvl, v_b, nullptr,
                                                 avh, avl, 0, 0, 0.f);

    // launch 5: attention (ncu -s 5 -c 1 captures THIS)
    cudaFuncSetAttribute(attn_mma, cudaFuncAttributeMaxDynamicSharedMemorySize, ATTN_SMEM);
    attn_mma<<<dim3(SQ / 128, NHEAD, NB), 256, ATTN_SMEM>>>(aqh, aql, akh, akl, avh, avl, oh, ol);

    // launch 6: output projection (fp32 out)
    mma_gemm<0><<<dim3(8, 32), 256, GEMM_SMEM>>>(oh, ol, woh, wol, out_b, out,
                                                 nullptr, nullptr, 0, 0, 0.f);
}

// round 14
// speedup vs baseline: 1.0777x; 1.0670x over previous
#include <cuda_runtime.h>
#include <cuda_bf16.h>
#include <math.h>
#include <stdint.h>

#define DMODEL 1024
#define NHEAD  16
#define HD     64
#define NB     4
#define SQ     1024
#define SK     2048

// ---------------------------------------------------------------------------
// Scratch (__device__ globals: allocation-free rule)
// ---------------------------------------------------------------------------
__device__ __nv_bfloat16 g_qh[NB * SQ * DMODEL];
__device__ __nv_bfloat16 g_ql[NB * SQ * DMODEL];
__device__ __nv_bfloat16 g_kvh[NB * SK * DMODEL];
__device__ __nv_bfloat16 g_kvl[NB * SK * DMODEL];
__device__ __nv_bfloat16 g_oh[NB * SQ * DMODEL];
__device__ __nv_bfloat16 g_ol[NB * SQ * DMODEL];
__device__ __nv_bfloat16 g_wqh[DMODEL * DMODEL];
__device__ __nv_bfloat16 g_wql[DMODEL * DMODEL];
__device__ __nv_bfloat16 g_wkh[DMODEL * DMODEL];
__device__ __nv_bfloat16 g_wkl[DMODEL * DMODEL];
__device__ __nv_bfloat16 g_wvh[DMODEL * DMODEL];
__device__ __nv_bfloat16 g_wvl[DMODEL * DMODEL];
__device__ __nv_bfloat16 g_woh[DMODEL * DMODEL];
__device__ __nv_bfloat16 g_wol[DMODEL * DMODEL];

// attention operands (bf16 hi/lo, post-RoPE, written by fused gemm epilogues)
__device__ __nv_bfloat16 g_aqh[NB * SQ * DMODEL];
__device__ __nv_bfloat16 g_aql[NB * SQ * DMODEL];
__device__ __nv_bfloat16 g_akh[NB * SK * DMODEL];
__device__ __nv_bfloat16 g_akl[NB * SK * DMODEL];
__device__ __nv_bfloat16 g_avh[NB * SK * DMODEL];
__device__ __nv_bfloat16 g_avl[NB * SK * DMODEL];

// ---------------------------------------------------------------------------
// Helpers
// ---------------------------------------------------------------------------
__device__ __forceinline__ uint32_t smem_u32(const void* p) {
    uint32_t a;
    asm("{ .reg .u64 t; cvta.to.shared.u64 t, %1; cvt.u32.u64 %0, t; }" : "=r"(a) : "l"(p));
    return a;
}
__device__ __forceinline__ void cp16(uint32_t dst, const void* src) {
    asm volatile("cp.async.cg.shared.global [%0], [%1], 16;" :: "r"(dst), "l"(src));
}
__device__ __forceinline__ void cp_commit() {
    asm volatile("cp.async.commit_group;" ::: "memory");
}
__device__ __forceinline__ void cp_wait1() {
    asm volatile("cp.async.wait_group 1;" ::: "memory");
}
__device__ __forceinline__ void cp_wait0() {
    asm volatile("cp.async.wait_group 0;" ::: "memory");
}
__device__ __forceinline__ void ldsm_x4(uint32_t addr, uint32_t* r) {
    asm volatile("ldmatrix.sync.aligned.m8n8.x4.shared.b16 {%0,%1,%2,%3}, [%4];"
                 : "=r"(r[0]), "=r"(r[1]), "=r"(r[2]), "=r"(r[3]) : "r"(addr));
}
__device__ __forceinline__ void ldsm_x4t(uint32_t addr, uint32_t* r) {
    asm volatile("ldmatrix.sync.aligned.m8n8.x4.trans.shared.b16 {%0,%1,%2,%3}, [%4];"
                 : "=r"(r[0]), "=r"(r[1]), "=r"(r[2]), "=r"(r[3]) : "r"(addr));
}
__device__ __forceinline__ void mma_bf16(float* d, const uint32_t* a, uint32_t b0, uint32_t b1) {
    asm volatile(
        "mma.sync.aligned.m16n8k16.row.col.f32.bf16.bf16.f32 "
        "{%0,%1,%2,%3}, {%4,%5,%6,%7}, {%8,%9}, {%0,%1,%2,%3};"
        : "+f"(d[0]), "+f"(d[1]), "+f"(d[2]), "+f"(d[3])
        : "r"(a[0]), "r"(a[1]), "r"(a[2]), "r"(a[3]), "r"(b0), "r"(b1));
}
// exp on the FMA pipe: 2^(x*log2e), deg-5 poly. rel err ~5e-7.
__device__ __forceinline__ float fast_exp(float x) {
    float y = fmaxf(x * 1.4426950408889634f, -100.0f);
    int n = __float2int_rn(y);
    float f = y - (float)n;
    float p = 1.3333558146e-3f;
    p = fmaf(p, f, 9.6181291076e-3f);
    p = fmaf(p, f, 5.5504108665e-2f);
    p = fmaf(p, f, 2.4022650696e-1f);
    p = fmaf(p, f, 6.9314718056e-1f);
    p = fmaf(p, f, 1.0f);
    return __int_as_float(__float_as_int(p) + (n << 23));
}
// split (a,b) fp32 pair -> bf16x2 hi + bf16x2 lo (lo = residual)
__device__ __forceinline__ void pack_split(float a, float b, uint32_t& hi2, uint32_t& lo2) {
    __nv_bfloat162 hb = __float22bfloat162_rn(make_float2(a, b));
    uint32_t h;
    memcpy(&h, &hb, 4);
    float ra = a - __uint_as_float(h << 16);
    float rb = b - __uint_as_float(h & 0xFFFF0000u);
    __nv_bfloat162 lb = __float22bfloat162_rn(make_float2(ra, rb));
    uint32_t l;
    memcpy(&l, &lb, 4);
    hi2 = h; lo2 = l;
}

// ---------------------------------------------------------------------------
// ONE split launch for all 6 fp32 sources (4 weights of 2^20 + query 4*2^20 +
// kv 8*2^20). Segment = (global elem idx) >> 20.
// ---------------------------------------------------------------------------
#define NWE (DMODEL * DMODEL)   // 2^20

__global__ void split_all(const float* __restrict__ q_w, const float* __restrict__ k_w,
                          const float* __restrict__ v_w, const float* __restrict__ o_w,
                          const float* __restrict__ query, const float* __restrict__ kvp,
                          __nv_bfloat16* __restrict__ wqh, __nv_bfloat16* __restrict__ wql,
                          __nv_bfloat16* __restrict__ wkh, __nv_bfloat16* __restrict__ wkl,
                          __nv_bfloat16* __restrict__ wvh, __nv_bfloat16* __restrict__ wvl,
                          __nv_bfloat16* __restrict__ woh, __nv_bfloat16* __restrict__ wol,
                          __nv_bfloat16* __restrict__ qh, __nv_bfloat16* __restrict__ ql,
                          __nv_bfloat16* __restrict__ kvh, __nv_bfloat16* __restrict__ kvl)
{
    const long long i = (long long)(blockIdx.x * blockDim.x + threadIdx.x) * 4;
    const int seg = (int)(i >> 20);
    const float* src;
    __nv_bfloat16 *hi, *lo;
    long long off;
    if (seg < 4) {
        off = i & (NWE - 1);
        switch (seg) {
            case 0:  src = q_w; hi = wqh; lo = wql; break;
            case 1:  src = k_w; hi = wkh; lo = wkl; break;
            case 2:  src = v_w; hi = wvh; lo = wvl; break;
            default: src = o_w; hi = woh; lo = wol; break;
        }
    } else if (seg < 8) {
        off = i - 4LL * NWE;
        src = query; hi = qh; lo = ql;
    } else {
        off = i - 8LL * NWE;
        src = kvp; hi = kvh; lo = kvl;
    }
    float4 v = *(const float4*)(src + off);
    uint32_t ha, la, hb, lb;
    pack_split(v.x, v.y, ha, la);
    pack_split(v.z, v.w, hb, lb);
    *(uint2*)(hi + off) = make_uint2(ha, hb);
    *(uint2*)(lo + off) = make_uint2(la, lb);
}

// ---------------------------------------------------------------------------
// Merged Q/K/V projection GEMM — ONE launch, grid (8, 160):
//   y <  32: Q rows  (RoPE stride 2, scale 1/8)
//   y <  96: K rows  (RoPE stride 1, scale 1)
//   else   : V rows  (plain split)
// Mainloop = exact R11 config (validated optimum). Epilogue mode is a runtime
// branch executed once per CTA.
// ---------------------------------------------------------------------------
#define GEMM_SMEM 65536
#define NCHUNK 48

__global__ __launch_bounds__(256, 2)
void mma_gemm_qkv(const __nv_bfloat16* __restrict__ qh, const __nv_bfloat16* __restrict__ ql,
                  const __nv_bfloat16* __restrict__ kvh, const __nv_bfloat16* __restrict__ kvl,
                  const __nv_bfloat16* __restrict__ wqh, const __nv_bfloat16* __restrict__ wql,
                  const __nv_bfloat16* __restrict__ wkh, const __nv_bfloat16* __restrict__ wkl,
                  const __nv_bfloat16* __restrict__ wvh, const __nv_bfloat16* __restrict__ wvl,
                  const float* __restrict__ q_b, const float* __restrict__ k_b,
                  const float* __restrict__ v_b,
                  __nv_bfloat16* __restrict__ aqh, __nv_bfloat16* __restrict__ aql,
                  __nv_bfloat16* __restrict__ akh, __nv_bfloat16* __restrict__ akl,
                  __nv_bfloat16* __restrict__ avh, __nv_bfloat16* __restrict__ avl)
{
    extern __shared__ char smc[];
    const uint32_t sbase = smem_u32(smc);
    const int tid = threadIdx.x;
    const int lane = tid & 31;
    const int wid = tid >> 5;
    const int warp_m = wid & 3;
    const int warp_n = wid >> 2;
    const int y = blockIdx.y;
    const int n0 = blockIdx.x * 128;

    // region select
    const __nv_bfloat16 *Ahi, *Alo, *Whi, *Wlo;
    const float* bias;
    __nv_bfloat16 *Oh, *Ol;
    int m0, L, posStride, doRope;
    float scale;
    if (y < 32) {
        Ahi = qh; Alo = ql; Whi = wqh; Wlo = wql; bias = q_b;
        Oh = aqh; Ol = aql; m0 = y * 128;
        L = SQ; posStride = 2; scale = 0.125f; doRope = 1;
    } else if (y < 96) {
        Ahi = kvh; Alo = kvl; Whi = wkh; Wlo = wkl; bias = k_b;
        Oh = akh; Ol = akl; m0 = (y - 32) * 128;
        L = SK; posStride = 1; scale = 1.0f; doRope = 1;
    } else {
        Ahi = kvh; Alo = kvl; Whi = wvh; Wlo = wvl; bias = v_b;
        Oh = avh; Ol = avl; m0 = (y - 96) * 128;
        L = 0; posStride = 0; scale = 0.f; doRope = 0;
    }

    const int lc = tid & 7;
    const int lr = tid >> 3;

    float acc[2][8][4];
#pragma unroll
    for (int mi = 0; mi < 2; mi++)
#pragma unroll
        for (int ni = 0; ni < 8; ni++)
#pragma unroll
            for (int e = 0; e < 4; e++) acc[mi][ni][e] = 0.f;

    auto issue_load = [&](int ci) {
        const int seg = ci >> 4;
        const int kk = (ci & 15) << 6;
        const __nv_bfloat16* As = (seg == 1) ? Alo : Ahi;
        const __nv_bfloat16* Ws = (seg == 2) ? Wlo : Whi;
        const uint32_t aoff = (ci & 1) ? 32768u : 0u;
        const uint32_t da = sbase + aoff;
        const uint32_t db = sbase + aoff + 16384u;
        const uint32_t sw = ((uint32_t)(lc ^ (lr & 7))) << 4;
#pragma unroll
        for (int p = 0; p < 4; p++) {
            const int r = lr + p * 32;
            const uint32_t so = (uint32_t)(r * 128) + sw;
            cp16(da + so, As + (size_t)(m0 + r) * DMODEL + kk + lc * 8);
            cp16(db + so, Ws + (size_t)(n0 + r) * DMODEL + kk + lc * 8);
        }
    };

    issue_load(0);
    cp_commit();

    for (int i = 0; i < NCHUNK; i++) {
        if (i + 1 < NCHUNK) {
            issue_load(i + 1);
            cp_commit();
            cp_wait1();
        } else {
            cp_wait0();
        }
        __syncthreads();

        const uint32_t aoff = (i & 1) ? 32768u : 0u;
        const uint32_t abase = sbase + aoff + (uint32_t)(warp_m * 32) * 128;
        const uint32_t bbase = sbase + aoff + 16384u + (uint32_t)(warp_n * 64) * 128;

#pragma unroll
        for (int ks = 0; ks < 4; ks++) {
            uint32_t afr[2][4];
#pragma unroll
            for (int mi = 0; mi < 2; mi++) {
                const int row = mi * 16 + (lane & 15);
                const int ch = ks * 2 + (lane >> 4);
                ldsm_x4(abase + (uint32_t)(row * 128) + (((uint32_t)(ch ^ (row & 7))) << 4),
                        afr[mi]);
            }
#pragma unroll
            for (int g = 0; g < 4; g++) {
                const int n = g * 16 + (lane & 7) + ((lane & 16) >> 1);
                const int ch = ks * 2 + ((lane >> 3) & 1);
                uint32_t bfr[4];
                ldsm_x4(bbase + (uint32_t)(n * 128) + (((uint32_t)(ch ^ (n & 7))) << 4), bfr);
#pragma unroll
                for (int mi = 0; mi < 2; mi++) {
                    mma_bf16(acc[mi][2 * g + 0], afr[mi], bfr[0], bfr[1]);
                    mma_bf16(acc[mi][2 * g + 1], afr[mi], bfr[2], bfr[3]);
                }
            }
        }
        __syncthreads();
    }

    // ---- fused epilogue (runtime mode) ----
    const int colb = n0 + warp_n * 64 + (lane & 3) * 2;

    if (!doRope) {
#pragma unroll
        for (int mi = 0; mi < 2; mi++) {
            const int row = m0 + warp_m * 32 + mi * 16 + (lane >> 2);
#pragma unroll
            for (int ni = 0; ni < 8; ni++) {
                const int col = colb + ni * 8;
                const float bx = bias[col], by = bias[col + 1];
                uint32_t h2, l2;
                pack_split(acc[mi][ni][0] + bx, acc[mi][ni][1] + by, h2, l2);
                *(uint32_t*)&Oh[(size_t)row * DMODEL + col] = h2;
                *(uint32_t*)&Ol[(size_t)row * DMODEL + col] = l2;
                pack_split(acc[mi][ni][2] + bx, acc[mi][ni][3] + by, h2, l2);
                *(uint32_t*)&Oh[(size_t)(row + 8) * DMODEL + col] = h2;
                *(uint32_t*)&Ol[(size_t)(row + 8) * DMODEL + col] = l2;
            }
        }
    } else {
        // RoPE pairs (j, j+32) are (ni, ni+4) — register-local.
#pragma unroll
        for (int mi = 0; mi < 2; mi++) {
#pragma unroll
            for (int half = 0; half < 2; half++) {
                const int row = m0 + warp_m * 32 + mi * 16 + (lane >> 2) + half * 8;
                const int eo = half * 2;
                const float pos = (float)((row % L) * posStride);
#pragma unroll
                for (int nj = 0; nj < 4; nj++) {
                    const int col = colb + nj * 8;
                    float y1[2], y2[2];
#pragma unroll
                    for (int el = 0; el < 2; el++) {
                        const int j32 = nj * 8 + (lane & 3) * 2 + el;
                        const float invf =
                            1.0f / powf(10000.0f, (float)j32 * (1.0f / 32.0f));
                        float s, c;
                        sincosf(pos * invf, &s, &c);
                        const float x1 = acc[mi][nj][eo + el] + bias[col + el];
                        const float x2 = acc[mi][nj + 4][eo + el] + bias[col + 32 + el];
                        y1[el] = (x1 * c - x2 * s) * scale;
                        y2[el] = (x2 * c + x1 * s) * scale;
                    }
                    uint32_t h2, l2;
                    pack_split(y1[0], y1[1], h2, l2);
                    *(uint32_t*)&Oh[(size_t)row * DMODEL + col] = h2;
                    *(uint32_t*)&Ol[(size_t)row * DMODEL + col] = l2;
                    pack_split(y2[0], y2[1], h2, l2);
                    *(uint32_t*)&Oh[(size_t)row * DMODEL + col + 32] = h2;
                    *(uint32_t*)&Ol[(size_t)row * DMODEL + col + 32] = l2;
                }
            }
        }
    }
}

// ---------------------------------------------------------------------------
// Output-projection GEMM (fp32 out) — exact R11 MODE 0.
// ---------------------------------------------------------------------------
__global__ __launch_bounds__(256, 2)
void mma_gemm_o(const __nv_bfloat16* __restrict__ Ahi, const __nv_bfloat16* __restrict__ Alo,
                const __nv_bfloat16* __restrict__ Whi, const __nv_bfloat16* __restrict__ Wlo,
                const float* __restrict__ bias, float* __restrict__ C)
{
    extern __shared__ char smc[];
    const uint32_t sbase = smem_u32(smc);
    const int tid = threadIdx.x;
    const int lane = tid & 31;
    const int wid = tid >> 5;
    const int warp_m = wid & 3;
    const int warp_n = wid >> 2;
    const int m0 = blockIdx.y * 128;
    const int n0 = blockIdx.x * 128;

    const int lc = tid & 7;
    const int lr = tid >> 3;

    float acc[2][8][4];
#pragma unroll
    for (int mi = 0; mi < 2; mi++)
#pragma unroll
        for (int ni = 0; ni < 8; ni++)
#pragma unroll
            for (int e = 0; e < 4; e++) acc[mi][ni][e] = 0.f;

    auto issue_load = [&](int ci) {
        const int seg = ci >> 4;
        const int kk = (ci & 15) << 6;
        const __nv_bfloat16* As = (seg == 1) ? Alo : Ahi;
        const __nv_bfloat16* Ws = (seg == 2) ? Wlo : Whi;
        const uint32_t aoff = (ci & 1) ? 32768u : 0u;
        const uint32_t da = sbase + aoff;
        const uint32_t db = sbase + aoff + 16384u;
        const uint32_t sw = ((uint32_t)(lc ^ (lr & 7))) << 4;
#pragma unroll
        for (int p = 0; p < 4; p++) {
            const int r = lr + p * 32;
            const uint32_t so = (uint32_t)(r * 128) + sw;
            cp16(da + so, As + (size_t)(m0 + r) * DMODEL + kk + lc * 8);
            cp16(db + so, Ws + (size_t)(n0 + r) * DMODEL + kk + lc * 8);
        }
    };

    issue_load(0);
    cp_commit();

    for (int i = 0; i < NCHUNK; i++) {
        if (i + 1 < NCHUNK) {
            issue_load(i + 1);
            cp_commit();
            cp_wait1();
        } else {
            cp_wait0();
        }
        __syncthreads();

        const uint32_t aoff = (i & 1) ? 32768u : 0u;
        const uint32_t abase = sbase + aoff + (uint32_t)(warp_m * 32) * 128;
        const uint32_t bbase = sbase + aoff + 16384u + (uint32_t)(warp_n * 64) * 128;

#pragma unroll
        for (int ks = 0; ks < 4; ks++) {
            uint32_t afr[2][4];
#pragma unroll
            for (int mi = 0; mi < 2; mi++) {
                const int row = mi * 16 + (lane & 15);
                const int ch = ks * 2 + (lane >> 4);
                ldsm_x4(abase + (uint32_t)(row * 128) + (((uint32_t)(ch ^ (row & 7))) << 4),
                        afr[mi]);
            }
#pragma unroll
            for (int g = 0; g < 4; g++) {
                const int n = g * 16 + (lane & 7) + ((lane & 16) >> 1);
                const int ch = ks * 2 + ((lane >> 3) & 1);
                uint32_t bfr[4];
                ldsm_x4(bbase + (uint32_t)(n * 128) + (((uint32_t)(ch ^ (n & 7))) << 4), bfr);
#pragma unroll
                for (int mi = 0; mi < 2; mi++) {
                    mma_bf16(acc[mi][2 * g + 0], afr[mi], bfr[0], bfr[1]);
                    mma_bf16(acc[mi][2 * g + 1], afr[mi], bfr[2], bfr[3]);
                }
            }
        }
        __syncthreads();
    }

    const int colb = n0 + warp_n * 64 + (lane & 3) * 2;
#pragma unroll
    for (int mi = 0; mi < 2; mi++) {
        const int row = m0 + warp_m * 32 + mi * 16 + (lane >> 2);
#pragma unroll
        for (int ni = 0; ni < 8; ni++) {
            const int col = colb + ni * 8;
            const float bx = bias[col], by = bias[col + 1];
            *(float2*)&C[(size_t)row * DMODEL + col] =
                make_float2(acc[mi][ni][0] + bx, acc[mi][ni][1] + by);
            *(float2*)&C[(size_t)(row + 8) * DMODEL + col] =
                make_float2(acc[mi][ni][2] + bx, acc[mi][ni][3] + by);
        }
    }
}

// ---------------------------------------------------------------------------
// Tensor-core flash attention — R8-validated config (unchanged).
// ---------------------------------------------------------------------------
#define ATTN_SMEM 81920
#define NKCH (SK / 64)

__global__ __launch_bounds__(256, 2)
void attn_mma(const __nv_bfloat16* __restrict__ Qh, const __nv_bfloat16* __restrict__ Ql,
              const __nv_bfloat16* __restrict__ Kh, const __nv_bfloat16* __restrict__ Kl,
              const __nv_bfloat16* __restrict__ Vh, const __nv_bfloat16* __restrict__ Vl,
              __nv_bfloat16* __restrict__ Oh, __nv_bfloat16* __restrict__ Ol)
{
    extern __shared__ char smc[];
    const uint32_t sbase = smem_u32(smc);
    const int tid = threadIdx.x;
    const int lane = tid & 31;
    const int wid = tid >> 5;
    const int b = blockIdx.z;
    const int h = blockIdx.y;
    const int s0 = blockIdx.x * 128;

    const uint32_t QLS = 0;
    const uint32_t STG0 = 16384;

    {
        const int r = tid >> 1;
        const int cb = (tid & 1) * 4;
        const size_t src = ((size_t)(b * SQ + s0 + r)) * DMODEL + h * HD;
#pragma unroll
        for (int u = 0; u < 4; u++) {
            const int c = cb + u;
            const uint32_t off = (uint32_t)(r * 128) + (((uint32_t)(c ^ (r & 7))) << 4);
            cp16(sbase + STG0 + off, Qh + src + c * 8);
            cp16(sbase + QLS + off, Ql + src + c * 8);
        }
    }
    cp_commit();
    cp_wait0();
    __syncthreads();

    uint32_t qfh[4][4];
    {
        const int row = wid * 16 + (lane & 15);
#pragma unroll
        for (int ks = 0; ks < 4; ks++) {
            const int ch = ks * 2 + (lane >> 4);
            const uint32_t off = (uint32_t)(row * 128) + (((uint32_t)(ch ^ (row & 7))) << 4);
            ldsm_x4(sbase + STG0 + off, qfh[ks]);
        }
    }
    __syncthreads();

    auto issue_kv = [&](int ci) {
        const uint32_t st = STG0 + (uint32_t)(ci & 1) * 32768u;
        const int r = tid >> 2;
        const int cb = (tid & 3) * 2;
        const size_t src = ((size_t)(b * SK + ci * 64 + r)) * DMODEL + h * HD;
#pragma unroll
        for (int u = 0; u < 2; u++) {
            const int c = cb + u;
            const uint32_t off = (uint32_t)(r * 128) + (((uint32_t)(c ^ (r & 7))) << 4);
            cp16(st + sbase + off, Kh + src + c * 8);
            cp16(st + sbase + 8192u + off, Kl + src + c * 8);
            cp16(st + sbase + 16384u + off, Vh + src + c * 8);
            cp16(st + sbase + 24576u + off, Vl + src + c * 8);
        }
    };

    issue_kv(0);
    cp_commit();

    float oacc[8][4];
#pragma unroll
    for (int g = 0; g < 8; g++)
#pragma unroll
        for (int e = 0; e < 4; e++) oacc[g][e] = 0.f;
    float m0 = -INFINITY, m1 = -INFINITY, l0 = 0.f, l1 = 0.f;

    const int qrow = wid * 16 + (lane & 15);

    for (int i = 0; i < NKCH; i++) {
        if (i + 1 < NKCH) {
            issue_kv(i + 1);
            cp_commit();
            cp_wait1();
        } else {
            cp_wait0();
        }
        __syncthreads();

        const uint32_t st = sbase + STG0 + (uint32_t)(i & 1) * 32768u;
        const uint32_t kh = st, kl = st + 8192u;
        const uint32_t vh = st + 16384u, vl = st + 24576u;

        float sacc[8][4];
#pragma unroll
        for (int g = 0; g < 8; g++)
#pragma unroll
            for (int e = 0; e < 4; e++) sacc[g][e] = 0.f;

#pragma unroll
        for (int ks = 0; ks < 4; ks++) {
            uint32_t qfl[4];
            {
                const int ch = ks * 2 + (lane >> 4);
                const uint32_t off =
                    (uint32_t)(qrow * 128) + (((uint32_t)(ch ^ (qrow & 7))) << 4);
                ldsm_x4(sbase + QLS + off, qfl);
            }
#pragma unroll
            for (int g = 0; g < 4; g++) {
                const int n = g * 16 + (lane & 7) + ((lane & 16) >> 1);
                const int ch = ks * 2 + ((lane >> 3) & 1);
                const uint32_t off = (uint32_t)(n * 128) + (((uint32_t)(ch ^ (n & 7))) << 4);
                uint32_t bh[4], bl[4];
                ldsm_x4(kh + off, bh);
                ldsm_x4(kl + off, bl);
                mma_bf16(sacc[2 * g + 0], qfh[ks], bh[0], bh[1]);
                mma_bf16(sacc[2 * g + 0], qfl, bh[0], bh[1]);
                mma_bf16(sacc[2 * g + 0], qfh[ks], bl[0], bl[1]);
                mma_bf16(sacc[2 * g + 1], qfh[ks], bh[2], bh[3]);
                mma_bf16(sacc[2 * g + 1], qfl, bh[2], bh[3]);
                mma_bf16(sacc[2 * g + 1], qfh[ks], bl[2], bl[3]);
            }
        }

        float mx0 = sacc[0][0], mx1 = sacc[0][2];
#pragma unroll
        for (int g = 0; g < 8; g++) {
            mx0 = fmaxf(mx0, fmaxf(sacc[g][0], sacc[g][1]));
            mx1 = fmaxf(mx1, fmaxf(sacc[g][2], sacc[g][3]));
        }
        mx0 = fmaxf(mx0, __shfl_xor_sync(0xffffffffu, mx0, 1));
        mx0 = fmaxf(mx0, __shfl_xor_sync(0xffffffffu, mx0, 2));
        mx1 = fmaxf(mx1, __shfl_xor_sync(0xffffffffu, mx1, 1));
        mx1 = fmaxf(mx1, __shfl_xor_sync(0xffffffffu, mx1, 2));
        const float mn0 = fmaxf(m0, mx0);
        const float mn1 = fmaxf(m1, mx1);
        const float a0 = fast_exp(m0 - mn0);
        const float a1 = fast_exp(m1 - mn1);
        m0 = mn0; m1 = mn1;
        float s0s = 0.f, s1s = 0.f;
#pragma unroll
        for (int g = 0; g < 8; g++) {
            sacc[g][0] = fast_exp(sacc[g][0] - mn0);
            sacc[g][1] = fast_exp(sacc[g][1] - mn0);
            sacc[g][2] = fast_exp(sacc[g][2] - mn1);
            sacc[g][3] = fast_exp(sacc[g][3] - mn1);
            s0s += sacc[g][0] + sacc[g][1];
            s1s += sacc[g][2] + sacc[g][3];
        }
        l0 = l0 * a0 + s0s;
        l1 = l1 * a1 + s1s;
#pragma unroll
        for (int g = 0; g < 8; g++) {
            oacc[g][0] *= a0; oacc[g][1] *= a0;
            oacc[g][2] *= a1; oacc[g][3] *= a1;
        }

#pragma unroll
        for (int ks = 0; ks < 4; ks++) {
            uint32_t ah[4], al[4];
            pack_split(sacc[2 * ks][0],     sacc[2 * ks][1],     ah[0], al[0]);
            pack_split(sacc[2 * ks][2],     sacc[2 * ks][3],     ah[1], al[1]);
            pack_split(sacc[2 * ks + 1][0], sacc[2 * ks + 1][1], ah[2], al[2]);
            pack_split(sacc[2 * ks + 1][2], sacc[2 * ks + 1][3], ah[3], al[3]);
            const int tile2 = lane >> 3;
            const int key = ks * 16 + (tile2 & 1) * 8 + (lane & 7);
#pragma unroll
            for (int g = 0; g < 4; g++) {
                const int c = g * 2 + (tile2 >> 1);
                const uint32_t off = (uint32_t)(key * 128) + (((uint32_t)(c ^ (key & 7))) << 4);
                uint32_t bh[4], bl[4];
                ldsm_x4t(vh + off, bh);
                ldsm_x4t(vl + off, bl);
                mma_bf16(oacc[2 * g + 0], ah, bh[0], bh[1]);
                mma_bf16(oacc[2 * g + 0], al, bh[0], bh[1]);
                mma_bf16(oacc[2 * g + 0], ah, bl[0], bl[1]);
                mma_bf16(oacc[2 * g + 1], ah, bh[2], bh[3]);
                mma_bf16(oacc[2 * g + 1], al, bh[2], bh[3]);
                mma_bf16(oacc[2 * g + 1], ah, bl[2], bl[3]);
            }
        }
        __syncthreads();
    }

    l0 += __shfl_xor_sync(0xffffffffu, l0, 1);
    l0 += __shfl_xor_sync(0xffffffffu, l0, 2);
    l1 += __shfl_xor_sync(0xffffffffu, l1, 1);
    l1 += __shfl_xor_sync(0xffffffffu, l1, 2);
    const float inv0 = 1.0f / l0;
    const float inv1 = 1.0f / l1;
    const int r0 = s0 + wid * 16 + (lane >> 2);
#pragma unroll
    for (int g = 0; g < 8; g++) {
        const int col = h * HD + g * 8 + (lane & 3) * 2;
        uint32_t h2, l2;
        pack_split(oacc[g][0] * inv0, oacc[g][1] * inv0, h2, l2);
        *(uint32_t*)&Oh[((size_t)(b * SQ) + r0) * DMODEL + col] = h2;
        *(uint32_t*)&Ol[((size_t)(b * SQ) + r0) * DMODEL + col] = l2;
        pack_split(oacc[g][2] * inv1, oacc[g][3] * inv1, h2, l2);
        *(uint32_t*)&Oh[((size_t)(b * SQ) + r0 + 8) * DMODEL + col] = h2;
        *(uint32_t*)&Ol[((size_t)(b * SQ) + r0 + 8) * DMODEL + col] = l2;
    }
}

// ---------------------------------------------------------------------------
extern "C" void kernel_launch(void* const* d_in, const int* in_sizes, int n_in,
                              void* d_out, int out_size)
{
    const float* query = (const float*)d_in[0];
    const float* kv    = (const float*)d_in[1];
    const float* q_w   = (const float*)d_in[2];
    const float* q_b   = (const float*)d_in[3];
    const float* k_w   = (const float*)d_in[4];
    const float* k_b   = (const float*)d_in[5];
    const float* v_w   = (const float*)d_in[6];
    const float* v_b   = (const float*)d_in[7];
    const float* out_w = (const float*)d_in[8];
    const float* out_b = (const float*)d_in[9];
    float* out = (float*)d_out;

    __nv_bfloat16 *qh, *ql, *kvh, *kvl, *oh, *ol;
    __nv_bfloat16 *wqh, *wql, *wkh, *wkl, *wvh, *wvl, *woh, *wol;
    __nv_bfloat16 *aqh, *aql, *akh, *akl, *avh, *avl;
    cudaGetSymbolAddress((void**)&qh,  g_qh);  cudaGetSymbolAddress((void**)&ql,  g_ql);
    cudaGetSymbolAddress((void**)&kvh, g_kvh); cudaGetSymbolAddress((void**)&kvl, g_kvl);
    cudaGetSymbolAddress((void**)&oh,  g_oh);  cudaGetSymbolAddress((void**)&ol,  g_ol);
    cudaGetSymbolAddress((void**)&wqh, g_wqh); cudaGetSymbolAddress((void**)&wql, g_wql);
    cudaGetSymbolAddress((void**)&wkh, g_wkh); cudaGetSymbolAddress((void**)&wkl, g_wkl);
    cudaGetSymbolAddress((void**)&wvh, g_wvh); cudaGetSymbolAddress((void**)&wvl, g_wvl);
    cudaGetSymbolAddress((void**)&woh, g_woh); cudaGetSymbolAddress((void**)&wol, g_wol);
    cudaGetSymbolAddress((void**)&aqh, g_aqh); cudaGetSymbolAddress((void**)&aql, g_aql);
    cudaGetSymbolAddress((void**)&akh, g_akh); cudaGetSymbolAddress((void**)&akl, g_akl);
    cudaGetSymbolAddress((void**)&avh, g_avh); cudaGetSymbolAddress((void**)&avl, g_avl);

    // launch 0: ALL splits in one kernel (16M elems)
    split_all<<<16384, 256>>>(q_w, k_w, v_w, out_w, query, kv,
                              wqh, wql, wkh, wkl, wvh, wvl, woh, wol,
                              qh, ql, kvh, kvl);

    // launch 1: merged Q/K/V projections (1280 CTAs — packs GEMM waves)
    cudaFuncSetAttribute(mma_gemm_qkv, cudaFuncAttributeMaxDynamicSharedMemorySize, GEMM_SMEM);
    mma_gemm_qkv<<<dim3(8, 160), 256, GEMM_SMEM>>>(qh, ql, kvh, kvl,
                                                   wqh, wql, wkh, wkl, wvh, wvl,
                                                   q_b, k_b, v_b,
                                                   aqh, aql, akh, akl, avh, avl);

    // launch 2: attention
    cudaFuncSetAttribute(attn_mma, cudaFuncAttributeMaxDynamicSharedMemorySize, ATTN_SMEM);
    attn_mma<<<dim3(SQ / 128, NHEAD, NB), 256, ATTN_SMEM>>>(aqh, aql, akh, akl, avh, avl, oh, ol);

    // launch 3: output projection (fp32 out)
    cudaFuncSetAttribute(mma_gemm_o, cudaFuncAttributeMaxDynamicSharedMemorySize, GEMM_SMEM);
    mma_gemm_o<<<dim3(8, 32), 256, GEMM_SMEM>>>(oh, ol, woh, wol, out_b, out);
}

// round 15
// speedup vs baseline: 1.2301x; 1.1414x over previous
#include <cuda_runtime.h>
#include <cuda_bf16.h>
#include <math.h>
#include <stdint.h>

#define DMODEL 1024
#define NHEAD  16
#define HD     64
#define NB     4
#define SQ     1024
#define SK     2048

// ---------------------------------------------------------------------------
// Scratch (__device__ globals)
// ---------------------------------------------------------------------------
// tf32-rounded fp32 GEMM operands
__device__ float g_qr[NB * SQ * DMODEL];     // 16 MB
__device__ float g_kvr[NB * SK * DMODEL];    // 32 MB
__device__ float g_wqr[DMODEL * DMODEL];
__device__ float g_wkr[DMODEL * DMODEL];
__device__ float g_wvr[DMODEL * DMODEL];
// bf16 hi/lo for the O-projection (kept 3-term bf16 for accuracy margin)
__device__ __nv_bfloat16 g_woh[DMODEL * DMODEL];
__device__ __nv_bfloat16 g_wol[DMODEL * DMODEL];
__device__ __nv_bfloat16 g_oh[NB * SQ * DMODEL];
__device__ __nv_bfloat16 g_ol[NB * SQ * DMODEL];
// attention operands (bf16 hi/lo, post-RoPE, written by fused gemm epilogues)
__device__ __nv_bfloat16 g_aqh[NB * SQ * DMODEL];
__device__ __nv_bfloat16 g_aql[NB * SQ * DMODEL];
__device__ __nv_bfloat16 g_akh[NB * SK * DMODEL];
__device__ __nv_bfloat16 g_akl[NB * SK * DMODEL];
__device__ __nv_bfloat16 g_avh[NB * SK * DMODEL];
__device__ __nv_bfloat16 g_avl[NB * SK * DMODEL];

// ---------------------------------------------------------------------------
// Helpers
// ---------------------------------------------------------------------------
__device__ __forceinline__ uint32_t smem_u32(const void* p) {
    uint32_t a;
    asm("{ .reg .u64 t; cvta.to.shared.u64 t, %1; cvt.u32.u64 %0, t; }" : "=r"(a) : "l"(p));
    return a;
}
__device__ __forceinline__ void cp16(uint32_t dst, const void* src) {
    asm volatile("cp.async.cg.shared.global [%0], [%1], 16;" :: "r"(dst), "l"(src));
}
__device__ __forceinline__ void cp_commit() {
    asm volatile("cp.async.commit_group;" ::: "memory");
}
__device__ __forceinline__ void cp_wait1() {
    asm volatile("cp.async.wait_group 1;" ::: "memory");
}
__device__ __forceinline__ void cp_wait0() {
    asm volatile("cp.async.wait_group 0;" ::: "memory");
}
__device__ __forceinline__ void ldsm_x4(uint32_t addr, uint32_t* r) {
    asm volatile("ldmatrix.sync.aligned.m8n8.x4.shared.b16 {%0,%1,%2,%3}, [%4];"
                 : "=r"(r[0]), "=r"(r[1]), "=r"(r[2]), "=r"(r[3]) : "r"(addr));
}
__device__ __forceinline__ void ldsm_x4t(uint32_t addr, uint32_t* r) {
    asm volatile("ldmatrix.sync.aligned.m8n8.x4.trans.shared.b16 {%0,%1,%2,%3}, [%4];"
                 : "=r"(r[0]), "=r"(r[1]), "=r"(r[2]), "=r"(r[3]) : "r"(addr));
}
__device__ __forceinline__ void mma_bf16(float* d, const uint32_t* a, uint32_t b0, uint32_t b1) {
    asm volatile(
        "mma.sync.aligned.m16n8k16.row.col.f32.bf16.bf16.f32 "
        "{%0,%1,%2,%3}, {%4,%5,%6,%7}, {%8,%9}, {%0,%1,%2,%3};"
        : "+f"(d[0]), "+f"(d[1]), "+f"(d[2]), "+f"(d[3])
        : "r"(a[0]), "r"(a[1]), "r"(a[2]), "r"(a[3]), "r"(b0), "r"(b1));
}
__device__ __forceinline__ void mma_tf32(float* d, const uint32_t* a, uint32_t b0, uint32_t b1) {
    asm volatile(
        "mma.sync.aligned.m16n8k8.row.col.f32.tf32.tf32.f32 "
        "{%0,%1,%2,%3}, {%4,%5,%6,%7}, {%8,%9}, {%0,%1,%2,%3};"
        : "+f"(d[0]), "+f"(d[1]), "+f"(d[2]), "+f"(d[3])
        : "r"(a[0]), "r"(a[1]), "r"(a[2]), "r"(a[3]), "r"(b0), "r"(b1));
}
__device__ __forceinline__ uint32_t rna_tf32(float x) {
    uint32_t r;
    asm("cvt.rna.tf32.f32 %0, %1;" : "=r"(r) : "f"(x));
    return r;
}
// exp on the FMA pipe: 2^(x*log2e), deg-5 poly. rel err ~5e-7.
__device__ __forceinline__ float fast_exp(float x) {
    float y = fmaxf(x * 1.4426950408889634f, -100.0f);
    int n = __float2int_rn(y);
    float f = y - (float)n;
    float p = 1.3333558146e-3f;
    p = fmaf(p, f, 9.6181291076e-3f);
    p = fmaf(p, f, 5.5504108665e-2f);
    p = fmaf(p, f, 2.4022650696e-1f);
    p = fmaf(p, f, 6.9314718056e-1f);
    p = fmaf(p, f, 1.0f);
    return __int_as_float(__float_as_int(p) + (n << 23));
}
// split (a,b) fp32 pair -> bf16x2 hi + bf16x2 lo (lo = residual)
__device__ __forceinline__ void pack_split(float a, float b, uint32_t& hi2, uint32_t& lo2) {
    __nv_bfloat162 hb = __float22bfloat162_rn(make_float2(a, b));
    uint32_t h;
    memcpy(&h, &hb, 4);
    float ra = a - __uint_as_float(h << 16);
    float rb = b - __uint_as_float(h & 0xFFFF0000u);
    __nv_bfloat162 lb = __float22bfloat162_rn(make_float2(ra, rb));
    uint32_t l;
    memcpy(&l, &lb, 4);
    hi2 = h; lo2 = l;
}

// ---------------------------------------------------------------------------
// ONE pre-pass: segs (each 2^20 elems):
//   0-2: q_w/k_w/v_w -> rna-rounded fp32
//   3:   out_w       -> bf16 hi/lo (O-proj stays bf16 3-term)
//   4-7: query       -> rna fp32
//   8-15: kv         -> rna fp32
// ---------------------------------------------------------------------------
#define NWE (DMODEL * DMODEL)

__global__ void round_all(const float* __restrict__ q_w, const float* __restrict__ k_w,
                          const float* __restrict__ v_w, const float* __restrict__ o_w,
                          const float* __restrict__ query, const float* __restrict__ kvp,
                          float* __restrict__ wqr, float* __restrict__ wkr,
                          float* __restrict__ wvr,
                          __nv_bfloat16* __restrict__ woh, __nv_bfloat16* __restrict__ wol,
                          float* __restrict__ qr, float* __restrict__ kvr)
{
    const long long i = (long long)(blockIdx.x * blockDim.x + threadIdx.x) * 4;
    const int seg = (int)(i >> 20);

    if (seg == 3) {   // out_w -> bf16 split
        const long long off = i & (NWE - 1);
        float4 v = *(const float4*)(o_w + off);
        uint32_t ha, la, hb, lb;
        pack_split(v.x, v.y, ha, la);
        pack_split(v.z, v.w, hb, lb);
        *(uint2*)(woh + off) = make_uint2(ha, hb);
        *(uint2*)(wol + off) = make_uint2(la, lb);
        return;
    }

    const float* src;
    float* dst;
    long long off;
    if (seg < 3) {
        off = i & (NWE - 1);
        src = (seg == 0) ? q_w : (seg == 1) ? k_w : v_w;
        dst = (seg == 0) ? wqr : (seg == 1) ? wkr : wvr;
    } else if (seg < 8) {
        off = i - 4LL * NWE;
        src = query; dst = qr;
    } else {
        off = i - 8LL * NWE;
        src = kvp; dst = kvr;
    }
    float4 v = *(const float4*)(src + off);
    float4 o;
    o.x = __uint_as_float(rna_tf32(v.x));
    o.y = __uint_as_float(rna_tf32(v.y));
    o.z = __uint_as_float(rna_tf32(v.z));
    o.w = __uint_as_float(rna_tf32(v.w));
    *(float4*)(dst + off) = o;
}

// ---------------------------------------------------------------------------
// tf32 single-pass merged Q/K/V projection GEMM. Grid (8, 160):
//   y<32: Q (RoPE stride2, scale 1/8); y<96: K (RoPE stride1); else V (split).
// 128x128 CTA tile, K-chunk = 32 fp32 (128B rows, same swizzle), NCHUNK = 32,
// double-buffered. Operands pre-rounded to tf32 -> no in-loop cvt.
// C-fragment layout identical to bf16 path -> same fused epilogues.
// ---------------------------------------------------------------------------
#define GEMM_SMEM 65536
#define NCH32 32

__global__ __launch_bounds__(256, 2)
void mma_gemm_qkv(const float* __restrict__ qr, const float* __restrict__ kvr,
                  const float* __restrict__ wqr, const float* __restrict__ wkr,
                  const float* __restrict__ wvr,
                  const float* __restrict__ q_b, const float* __restrict__ k_b,
                  const float* __restrict__ v_b,
                  __nv_bfloat16* __restrict__ aqh, __nv_bfloat16* __restrict__ aql,
                  __nv_bfloat16* __restrict__ akh, __nv_bfloat16* __restrict__ akl,
                  __nv_bfloat16* __restrict__ avh, __nv_bfloat16* __restrict__ avl)
{
    extern __shared__ char smc[];
    const uint32_t sbase = smem_u32(smc);
    const int tid = threadIdx.x;
    const int lane = tid & 31;
    const int wid = tid >> 5;
    const int warp_m = wid & 3;
    const int warp_n = wid >> 2;
    const int y = blockIdx.y;
    const int n0 = blockIdx.x * 128;

    const float *A, *W, *bias;
    __nv_bfloat16 *Oh, *Ol;
    int m0, L, posStride, doRope;
    float scale;
    if (y < 32) {
        A = qr; W = wqr; bias = q_b; Oh = aqh; Ol = aql; m0 = y * 128;
        L = SQ; posStride = 2; scale = 0.125f; doRope = 1;
    } else if (y < 96) {
        A = kvr; W = wkr; bias = k_b; Oh = akh; Ol = akl; m0 = (y - 32) * 128;
        L = SK; posStride = 1; scale = 1.0f; doRope = 1;
    } else {
        A = kvr; W = wvr; bias = v_b; Oh = avh; Ol = avl; m0 = (y - 96) * 128;
        L = 0; posStride = 0; scale = 0.f; doRope = 0;
    }

    const int lc = tid & 7;
    const int lr = tid >> 3;

    float acc[2][8][4];
#pragma unroll
    for (int mi = 0; mi < 2; mi++)
#pragma unroll
        for (int ni = 0; ni < 8; ni++)
#pragma unroll
            for (int e = 0; e < 4; e++) acc[mi][ni][e] = 0.f;

    auto issue_load = [&](int ci) {
        const int kk = ci * 32;                       // fp32 elems
        const uint32_t st = (ci & 1) ? 32768u : 0u;
        const uint32_t da = sbase + st;
        const uint32_t db = sbase + st + 16384u;
        const uint32_t sw = ((uint32_t)(lc ^ (lr & 7))) << 4;
#pragma unroll
        for (int p = 0; p < 4; p++) {
            const int r = lr + p * 32;
            const uint32_t so = (uint32_t)(r * 128) + sw;
            cp16(da + so, A + (size_t)(m0 + r) * DMODEL + kk + lc * 4);
            cp16(db + so, W + (size_t)(n0 + r) * DMODEL + kk + lc * 4);
        }
    };

    issue_load(0);
    cp_commit();

    for (int i = 0; i < NCH32; i++) {
        if (i + 1 < NCH32) {
            issue_load(i + 1);
            cp_commit();
            cp_wait1();
        } else {
            cp_wait0();
        }
        __syncthreads();

        const uint32_t st = (i & 1) ? 32768u : 0u;
        const uint32_t abase = sbase + st + (uint32_t)(warp_m * 32) * 128;
        const uint32_t bbase = sbase + st + 16384u + (uint32_t)(warp_n * 64) * 128;

#pragma unroll
        for (int ksp = 0; ksp < 2; ksp++) {
            uint32_t af[2][2][4];   // [mi][kss]
#pragma unroll
            for (int mi = 0; mi < 2; mi++)
#pragma unroll
                for (int kss = 0; kss < 2; kss++) {
                    const int ks = ksp * 2 + kss;
                    const int row = mi * 16 + (lane & 15);
                    const int c16 = ks * 2 + (lane >> 4);
                    ldsm_x4(abase + (uint32_t)(row * 128) +
                            (((uint32_t)(c16 ^ (row & 7))) << 4), af[mi][kss]);
                }
#pragma unroll
            for (int g = 0; g < 8; g++) {
                const int rowb = g * 8 + (lane & 7);
                const int c16 = ksp * 4 + (lane >> 3);
                uint32_t bf4[4];
                ldsm_x4(bbase + (uint32_t)(rowb * 128) +
                        (((uint32_t)(c16 ^ (rowb & 7))) << 4), bf4);
#pragma unroll
                for (int mi = 0; mi < 2; mi++) {
                    mma_tf32(acc[mi][g], af[mi][0], bf4[0], bf4[1]);
                    mma_tf32(acc[mi][g], af[mi][1], bf4[2], bf4[3]);
                }
            }
        }
        __syncthreads();
    }

    // ---- fused epilogue (same C layout as bf16 path) ----
    const int colb = n0 + warp_n * 64 + (lane & 3) * 2;

    if (!doRope) {
#pragma unroll
        for (int mi = 0; mi < 2; mi++) {
            const int row = m0 + warp_m * 32 + mi * 16 + (lane >> 2);
#pragma unroll
            for (int ni = 0; ni < 8; ni++) {
                const int col = colb + ni * 8;
                const float bx = bias[col], by = bias[col + 1];
                uint32_t h2, l2;
                pack_split(acc[mi][ni][0] + bx, acc[mi][ni][1] + by, h2, l2);
                *(uint32_t*)&Oh[(size_t)row * DMODEL + col] = h2;
                *(uint32_t*)&Ol[(size_t)row * DMODEL + col] = l2;
                pack_split(acc[mi][ni][2] + bx, acc[mi][ni][3] + by, h2, l2);
                *(uint32_t*)&Oh[(size_t)(row + 8) * DMODEL + col] = h2;
                *(uint32_t*)&Ol[(size_t)(row + 8) * DMODEL + col] = l2;
            }
        }
    } else {
#pragma unroll
        for (int mi = 0; mi < 2; mi++) {
#pragma unroll
            for (int half = 0; half < 2; half++) {
                const int row = m0 + warp_m * 32 + mi * 16 + (lane >> 2) + half * 8;
                const int eo = half * 2;
                const float pos = (float)((row % L) * posStride);
#pragma unroll
                for (int nj = 0; nj < 4; nj++) {
                    const int col = colb + nj * 8;
                    float y1[2], y2[2];
#pragma unroll
                    for (int el = 0; el < 2; el++) {
                        const int j32 = nj * 8 + (lane & 3) * 2 + el;
                        const float invf =
                            1.0f / powf(10000.0f, (float)j32 * (1.0f / 32.0f));
                        float s, c;
                        sincosf(pos * invf, &s, &c);
                        const float x1 = acc[mi][nj][eo + el] + bias[col + el];
                        const float x2 = acc[mi][nj + 4][eo + el] + bias[col + 32 + el];
                        y1[el] = (x1 * c - x2 * s) * scale;
                        y2[el] = (x2 * c + x1 * s) * scale;
                    }
                    uint32_t h2, l2;
                    pack_split(y1[0], y1[1], h2, l2);
                    *(uint32_t*)&Oh[(size_t)row * DMODEL + col] = h2;
                    *(uint32_t*)&Ol[(size_t)row * DMODEL + col] = l2;
                    pack_split(y2[0], y2[1], h2, l2);
                    *(uint32_t*)&Oh[(size_t)row * DMODEL + col + 32] = h2;
                    *(uint32_t*)&Ol[(size_t)row * DMODEL + col + 32] = l2;
                }
            }
        }
    }
}

// ---------------------------------------------------------------------------
// Output-projection GEMM — bf16 3-term (R11/R14-validated, kept for accuracy).
// ---------------------------------------------------------------------------
#define NCHUNK 48

__global__ __launch_bounds__(256, 2)
void mma_gemm_o(const __nv_bfloat16* __restrict__ Ahi, const __nv_bfloat16* __restrict__ Alo,
                const __nv_bfloat16* __restrict__ Whi, const __nv_bfloat16* __restrict__ Wlo,
                const float* __restrict__ bias, float* __restrict__ C)
{
    extern __shared__ char smc[];
    const uint32_t sbase = smem_u32(smc);
    const int tid = threadIdx.x;
    const int lane = tid & 31;
    const int wid = tid >> 5;
    const int warp_m = wid & 3;
    const int warp_n = wid >> 2;
    const int m0 = blockIdx.y * 128;
    const int n0 = blockIdx.x * 128;

    const int lc = tid & 7;
    const int lr = tid >> 3;

    float acc[2][8][4];
#pragma unroll
    for (int mi = 0; mi < 2; mi++)
#pragma unroll
        for (int ni = 0; ni < 8; ni++)
#pragma unroll
            for (int e = 0; e < 4; e++) acc[mi][ni][e] = 0.f;

    auto issue_load = [&](int ci) {
        const int seg = ci >> 4;
        const int kk = (ci & 15) << 6;
        const __nv_bfloat16* As = (seg == 1) ? Alo : Ahi;
        const __nv_bfloat16* Ws = (seg == 2) ? Wlo : Whi;
        const uint32_t aoff = (ci & 1) ? 32768u : 0u;
        const uint32_t da = sbase + aoff;
        const uint32_t db = sbase + aoff + 16384u;
        const uint32_t sw = ((uint32_t)(lc ^ (lr & 7))) << 4;
#pragma unroll
        for (int p = 0; p < 4; p++) {
            const int r = lr + p * 32;
            const uint32_t so = (uint32_t)(r * 128) + sw;
            cp16(da + so, As + (size_t)(m0 + r) * DMODEL + kk + lc * 8);
            cp16(db + so, Ws + (size_t)(n0 + r) * DMODEL + kk + lc * 8);
        }
    };

    issue_load(0);
    cp_commit();

    for (int i = 0; i < NCHUNK; i++) {
        if (i + 1 < NCHUNK) {
            issue_load(i + 1);
            cp_commit();
            cp_wait1();
        } else {
            cp_wait0();
        }
        __syncthreads();

        const uint32_t aoff = (i & 1) ? 32768u : 0u;
        const uint32_t abase = sbase + aoff + (uint32_t)(warp_m * 32) * 128;
        const uint32_t bbase = sbase + aoff + 16384u + (uint32_t)(warp_n * 64) * 128;

#pragma unroll
        for (int ks = 0; ks < 4; ks++) {
            uint32_t afr[2][4];
#pragma unroll
            for (int mi = 0; mi < 2; mi++) {
                const int row = mi * 16 + (lane & 15);
                const int ch = ks * 2 + (lane >> 4);
                ldsm_x4(abase + (uint32_t)(row * 128) + (((uint32_t)(ch ^ (row & 7))) << 4),
                        afr[mi]);
            }
#pragma unroll
            for (int g = 0; g < 4; g++) {
                const int n = g * 16 + (lane & 7) + ((lane & 16) >> 1);
                const int ch = ks * 2 + ((lane >> 3) & 1);
                uint32_t bfr[4];
                ldsm_x4(bbase + (uint32_t)(n * 128) + (((uint32_t)(ch ^ (n & 7))) << 4), bfr);
#pragma unroll
                for (int mi = 0; mi < 2; mi++) {
                    mma_bf16(acc[mi][2 * g + 0], afr[mi], bfr[0], bfr[1]);
                    mma_bf16(acc[mi][2 * g + 1], afr[mi], bfr[2], bfr[3]);
                }
            }
        }
        __syncthreads();
    }

    const int colb = n0 + warp_n * 64 + (lane & 3) * 2;
#pragma unroll
    for (int mi = 0; mi < 2; mi++) {
        const int row = m0 + warp_m * 32 + mi * 16 + (lane >> 2);
#pragma unroll
        for (int ni = 0; ni < 8; ni++) {
            const int col = colb + ni * 8;
            const float bx = bias[col], by = bias[col + 1];
            *(float2*)&C[(size_t)row * DMODEL + col] =
                make_float2(acc[mi][ni][0] + bx, acc[mi][ni][1] + by);
            *(float2*)&C[(size_t)(row + 8) * DMODEL + col] =
                make_float2(acc[mi][ni][2] + bx, acc[mi][ni][3] + by);
        }
    }
}

// ---------------------------------------------------------------------------
// Tensor-core flash attention — R8/R14-validated config (unchanged).
// ---------------------------------------------------------------------------
#define ATTN_SMEM 81920
#define NKCH (SK / 64)

__global__ __launch_bounds__(256, 2)
void attn_mma(const __nv_bfloat16* __restrict__ Qh, const __nv_bfloat16* __restrict__ Ql,
              const __nv_bfloat16* __restrict__ Kh, const __nv_bfloat16* __restrict__ Kl,
              const __nv_bfloat16* __restrict__ Vh, const __nv_bfloat16* __restrict__ Vl,
              __nv_bfloat16* __restrict__ Oh, __nv_bfloat16* __restrict__ Ol)
{
    extern __shared__ char smc[];
    const uint32_t sbase = smem_u32(smc);
    const int tid = threadIdx.x;
    const int lane = tid & 31;
    const int wid = tid >> 5;
    const int b = blockIdx.z;
    const int h = blockIdx.y;
    const int s0 = blockIdx.x * 128;

    const uint32_t QLS = 0;
    const uint32_t STG0 = 16384;

    {
        const int r = tid >> 1;
        const int cb = (tid & 1) * 4;
        const size_t src = ((size_t)(b * SQ + s0 + r)) * DMODEL + h * HD;
#pragma unroll
        for (int u = 0; u < 4; u++) {
            const int c = cb + u;
            const uint32_t off = (uint32_t)(r * 128) + (((uint32_t)(c ^ (r & 7))) << 4);
            cp16(sbase + STG0 + off, Qh + src + c * 8);
            cp16(sbase + QLS + off, Ql + src + c * 8);
        }
    }
    cp_commit();
    cp_wait0();
    __syncthreads();

    uint32_t qfh[4][4];
    {
        const int row = wid * 16 + (lane & 15);
#pragma unroll
        for (int ks = 0; ks < 4; ks++) {
            const int ch = ks * 2 + (lane >> 4);
            const uint32_t off = (uint32_t)(row * 128) + (((uint32_t)(ch ^ (row & 7))) << 4);
            ldsm_x4(sbase + STG0 + off, qfh[ks]);
        }
    }
    __syncthreads();

    auto issue_kv = [&](int ci) {
        const uint32_t st = STG0 + (uint32_t)(ci & 1) * 32768u;
        const int r = tid >> 2;
        const int cb = (tid & 3) * 2;
        const size_t src = ((size_t)(b * SK + ci * 64 + r)) * DMODEL + h * HD;
#pragma unroll
        for (int u = 0; u < 2; u++) {
            const int c = cb + u;
            const uint32_t off = (uint32_t)(r * 128) + (((uint32_t)(c ^ (r & 7))) << 4);
            cp16(st + sbase + off, Kh + src + c * 8);
            cp16(st + sbase + 8192u + off, Kl + src + c * 8);
            cp16(st + sbase + 16384u + off, Vh + src + c * 8);
            cp16(st + sbase + 24576u + off, Vl + src + c * 8);
        }
    };

    issue_kv(0);
    cp_commit();

    float oacc[8][4];
#pragma unroll
    for (int g = 0; g < 8; g++)
#pragma unroll
        for (int e = 0; e < 4; e++) oacc[g][e] = 0.f;
    float m0 = -INFINITY, m1 = -INFINITY, l0 = 0.f, l1 = 0.f;

    const int qrow = wid * 16 + (lane & 15);

    for (int i = 0; i < NKCH; i++) {
        if (i + 1 < NKCH) {
            issue_kv(i + 1);
            cp_commit();
            cp_wait1();
        } else {
            cp_wait0();
        }
        __syncthreads();

        const uint32_t st = sbase + STG0 + (uint32_t)(i & 1) * 32768u;
        const uint32_t kh = st, kl = st + 8192u;
        const uint32_t vh = st + 16384u, vl = st + 24576u;

        float sacc[8][4];
#pragma unroll
        for (int g = 0; g < 8; g++)
#pragma unroll
            for (int e = 0; e < 4; e++) sacc[g][e] = 0.f;

#pragma unroll
        for (int ks = 0; ks < 4; ks++) {
            uint32_t qfl[4];
            {
                const int ch = ks * 2 + (lane >> 4);
                const uint32_t off =
                    (uint32_t)(qrow * 128) + (((uint32_t)(ch ^ (qrow & 7))) << 4);
                ldsm_x4(sbase + QLS + off, qfl);
            }
#pragma unroll
            for (int g = 0; g < 4; g++) {
                const int n = g * 16 + (lane & 7) + ((lane & 16) >> 1);
                const int ch = ks * 2 + ((lane >> 3) & 1);
                const uint32_t off = (uint32_t)(n * 128) + (((uint32_t)(ch ^ (n & 7))) << 4);
                uint32_t bh[4], bl[4];
                ldsm_x4(kh + off, bh);
                ldsm_x4(kl + off, bl);
                mma_bf16(sacc[2 * g + 0], qfh[ks], bh[0], bh[1]);
                mma_bf16(sacc[2 * g + 0], qfl, bh[0], bh[1]);
                mma_bf16(sacc[2 * g + 0], qfh[ks], bl[0], bl[1]);
                mma_bf16(sacc[2 * g + 1], qfh[ks], bh[2], bh[3]);
                mma_bf16(sacc[2 * g + 1], qfl, bh[2], bh[3]);
                mma_bf16(sacc[2 * g + 1], qfh[ks], bl[2], bl[3]);
            }
        }

        float mx0 = sacc[0][0], mx1 = sacc[0][2];
#pragma unroll
        for (int g = 0; g < 8; g++) {
            mx0 = fmaxf(mx0, fmaxf(sacc[g][0], sacc[g][1]));
            mx1 = fmaxf(mx1, fmaxf(sacc[g][2], sacc[g][3]));
        }
        mx0 = fmaxf(mx0, __shfl_xor_sync(0xffffffffu, mx0, 1));
        mx0 = fmaxf(mx0, __shfl_xor_sync(0xffffffffu, mx0, 2));
        mx1 = fmaxf(mx1, __shfl_xor_sync(0xffffffffu, mx1, 1));
        mx1 = fmaxf(mx1, __shfl_xor_sync(0xffffffffu, mx1, 2));
        const float mn0 = fmaxf(m0, mx0);
        const float mn1 = fmaxf(m1, mx1);
        const float a0 = fast_exp(m0 - mn0);
        const float a1 = fast_exp(m1 - mn1);
        m0 = mn0; m1 = mn1;
        float s0s = 0.f, s1s = 0.f;
#pragma unroll
        for (int g = 0; g < 8; g++) {
            sacc[g][0] = fast_exp(sacc[g][0] - mn0);
            sacc[g][1] = fast_exp(sacc[g][1] - mn0);
            sacc[g][2] = fast_exp(sacc[g][2] - mn1);
            sacc[g][3] = fast_exp(sacc[g][3] - mn1);
            s0s += sacc[g][0] + sacc[g][1];
            s1s += sacc[g][2] + sacc[g][3];
        }
        l0 = l0 * a0 + s0s;
        l1 = l1 * a1 + s1s;
#pragma unroll
        for (int g = 0; g < 8; g++) {
            oacc[g][0] *= a0; oacc[g][1] *= a0;
            oacc[g][2] *= a1; oacc[g][3] *= a1;
        }

#pragma unroll
        for (int ks = 0; ks < 4; ks++) {
            uint32_t ah[4], al[4];
            pack_split(sacc[2 * ks][0],     sacc[2 * ks][1],     ah[0], al[0]);
            pack_split(sacc[2 * ks][2],     sacc[2 * ks][3],     ah[1], al[1]);
            pack_split(sacc[2 * ks + 1][0], sacc[2 * ks + 1][1], ah[2], al[2]);
            pack_split(sacc[2 * ks + 1][2], sacc[2 * ks + 1][3], ah[3], al[3]);
            const int tile2 = lane >> 3;
            const int key = ks * 16 + (tile2 & 1) * 8 + (lane & 7);
#pragma unroll
            for (int g = 0; g < 4; g++) {
                const int c = g * 2 + (tile2 >> 1);
                const uint32_t off = (uint32_t)(key * 128) + (((uint32_t)(c ^ (key & 7))) << 4);
                uint32_t bh[4], bl[4];
                ldsm_x4t(vh + off, bh);
                ldsm_x4t(vl + off, bl);
                mma_bf16(oacc[2 * g + 0], ah, bh[0], bh[1]);
                mma_bf16(oacc[2 * g + 0], al, bh[0], bh[1]);
                mma_bf16(oacc[2 * g + 0], ah, bl[0], bl[1]);
                mma_bf16(oacc[2 * g + 1], ah, bh[2], bh[3]);
                mma_bf16(oacc[2 * g + 1], al, bh[2], bh[3]);
                mma_bf16(oacc[2 * g + 1], ah, bl[2], bl[3]);
            }
        }
        __syncthreads();
    }

    l0 += __shfl_xor_sync(0xffffffffu, l0, 1);
    l0 += __shfl_xor_sync(0xffffffffu, l0, 2);
    l1 += __shfl_xor_sync(0xffffffffu, l1, 1);
    l1 += __shfl_xor_sync(0xffffffffu, l1, 2);
    const float inv0 = 1.0f / l0;
    const float inv1 = 1.0f / l1;
    const int r0 = s0 + wid * 16 + (lane >> 2);
#pragma unroll
    for (int g = 0; g < 8; g++) {
        const int col = h * HD + g * 8 + (lane & 3) * 2;
        uint32_t h2, l2;
        pack_split(oacc[g][0] * inv0, oacc[g][1] * inv0, h2, l2);
        *(uint32_t*)&Oh[((size_t)(b * SQ) + r0) * DMODEL + col] = h2;
        *(uint32_t*)&Ol[((size_t)(b * SQ) + r0) * DMODEL + col] = l2;
        pack_split(oacc[g][2] * inv1, oacc[g][3] * inv1, h2, l2);
        *(uint32_t*)&Oh[((size_t)(b * SQ) + r0 + 8) * DMODEL + col] = h2;
        *(uint32_t*)&Ol[((size_t)(b * SQ) + r0 + 8) * DMODEL + col] = l2;
    }
}

// ---------------------------------------------------------------------------
extern "C" void kernel_launch(void* const* d_in, const int* in_sizes, int n_in,
                              void* d_out, int out_size)
{
    const float* query = (const float*)d_in[0];
    const float* kv    = (const float*)d_in[1];
    const float* q_w   = (const float*)d_in[2];
    const float* q_b   = (const float*)d_in[3];
    const float* k_w   = (const float*)d_in[4];
    const float* k_b   = (const float*)d_in[5];
    const float* v_w   = (const float*)d_in[6];
    const float* v_b   = (const float*)d_in[7];
    const float* out_w = (const float*)d_in[8];
    const float* out_b = (const float*)d_in[9];
    float* out = (float*)d_out;

    float *qr, *kvr, *wqr, *wkr, *wvr;
    __nv_bfloat16 *woh, *wol, *oh, *ol;
    __nv_bfloat16 *aqh, *aql, *akh, *akl, *avh, *avl;
    cudaGetSymbolAddress((void**)&qr,  g_qr);  cudaGetSymbolAddress((void**)&kvr, g_kvr);
    cudaGetSymbolAddress((void**)&wqr, g_wqr); cudaGetSymbolAddress((void**)&wkr, g_wkr);
    cudaGetSymbolAddress((void**)&wvr, g_wvr);
    cudaGetSymbolAddress((void**)&woh, g_woh); cudaGetSymbolAddress((void**)&wol, g_wol);
    cudaGetSymbolAddress((void**)&oh,  g_oh);  cudaGetSymbolAddress((void**)&ol,  g_ol);
    cudaGetSymbolAddress((void**)&aqh, g_aqh); cudaGetSymbolAddress((void**)&aql, g_aql);
    cudaGetSymbolAddress((void**)&akh, g_akh); cudaGetSymbolAddress((void**)&akl, g_akl);
    cudaGetSymbolAddress((void**)&avh, g_avh); cudaGetSymbolAddress((void**)&avl, g_avl);

    // launch 0: rna-round GEMM operands + bf16-split out_w (16M elems)
    round_all<<<16384, 256>>>(q_w, k_w, v_w, out_w, query, kv,
                              wqr, wkr, wvr, woh, wol, qr, kvr);

    // launch 1: merged tf32 Q/K/V projections (1280 CTAs)
    cudaFuncSetAttribute(mma_gemm_qkv, cudaFuncAttributeMaxDynamicSharedMemorySize, GEMM_SMEM);
    mma_gemm_qkv<<<dim3(8, 160), 256, GEMM_SMEM>>>(qr, kvr, wqr, wkr, wvr,
                                                   q_b, k_b, v_b,
                                                   aqh, aql, akh, akl, avh, avl);

    // launch 2: attention (bf16 3-term, unchanged)
    cudaFuncSetAttribute(attn_mma, cudaFuncAttributeMaxDynamicSharedMemorySize, ATTN_SMEM);
    attn_mma<<<dim3(SQ / 128, NHEAD, NB), 256, ATTN_SMEM>>>(aqh, aql, akh, akl, avh, avl, oh, ol);

    // launch 3: output projection (bf16 3-term, fp32 out)
    cudaFuncSetAttribute(mma_gemm_o, cudaFuncAttributeMaxDynamicSharedMemorySize, GEMM_SMEM);
    mma_gemm_o<<<dim3(8, 32), 256, GEMM_SMEM>>>(oh, ol, woh, wol, out_b, out);
}